// round 3
// baseline (speedup 1.0000x reference)
#include <cuda_runtime.h>
#include <stdint.h>

#define NFULL 512
#define DIMF  64
#define H1    260   // 2*EIN
#define MD    17
#define CHID  68
#define NMAX  460
#define RPB   8     // rows per block (4 warps x 2 rows)
#define NSPL  5     // j-chunk split factor

typedef unsigned long long ull;

// ---------------- device scratch ----------------
__device__ uint32_t g_ugbits[NFULL*16];
__device__ uint32_t g_ug2bits[NFULL*16];
__device__ float    g_scores[NFULL];
__device__ int      g_idx[NFULL];
__device__ uint32_t g_gsub[NMAX*16];
__device__ float    g_hc[NMAX*DIMF];
__device__ float    g_cA[NMAX*3];
__device__ float    g_cB[NMAX*3];
__device__ float    g_Arow[NMAX*H1];
__device__ float    g_Brow[NMAX*H1];
__device__ float    g_mi[NMAX*MD];

// ---------------- f32x2 + fast-math helpers ----------------
__device__ __forceinline__ ull pk2(float lo, float hi){
    ull r;
    asm("mov.b64 %0, {%1,%2};" : "=l"(r) : "r"(__float_as_uint(lo)), "r"(__float_as_uint(hi)));
    return r;
}
__device__ __forceinline__ void unpk(ull v, float& lo, float& hi){
    unsigned a, b;
    asm("mov.b64 {%0,%1}, %2;" : "=r"(a), "=r"(b) : "l"(v));
    lo = __uint_as_float(a); hi = __uint_as_float(b);
}
__device__ __forceinline__ ull dup2(float v){ return pk2(v, v); }
__device__ __forceinline__ ull fma2(ull a, ull b, ull c){
    ull d; asm("fma.rn.f32x2 %0, %1, %2, %3;" : "=l"(d) : "l"(a), "l"(b), "l"(c)); return d;
}
__device__ __forceinline__ ull add2(ull a, ull b){
    ull d; asm("add.rn.f32x2 %0, %1, %2;" : "=l"(d) : "l"(a), "l"(b)); return d;
}
__device__ __forceinline__ ull mul2(ull a, ull b){
    ull d; asm("mul.rn.f32x2 %0, %1, %2;" : "=l"(d) : "l"(a), "l"(b)); return d;
}
__device__ __forceinline__ float ex2a(float x){ float y; asm("ex2.approx.ftz.f32 %0, %1;" : "=f"(y) : "f"(x)); return y; }
__device__ __forceinline__ float rcpa(float x){ float y; asm("rcp.approx.ftz.f32 %0, %1;" : "=f"(y) : "f"(x)); return y; }

__device__ __forceinline__ float siluf(float x){
    // x / (1 + exp(-x)) = x * rcp(1 + 2^(-x*log2e))
    return x * rcpa(1.0f + ex2a(-1.4426950408889634f * x));
}
// packed silu over 2 lanes
__device__ __forceinline__ ull silu2(ull x, ull NL2E, ull ONE2){
    ull t = mul2(x, NL2E);
    float t0, t1; unpk(t, t0, t1);
    ull e = add2(pk2(ex2a(t0), ex2a(t1)), ONE2);
    float u0, u1; unpk(e, u0, u1);
    ull r = pk2(rcpa(u0), rcpa(u1));
    return mul2(x, r);
}

// ---------------- misc kernels ----------------
__global__ void k_zero_out(float* out){
    int t = blockIdx.x*blockDim.x + threadIdx.x;
    if (t < NFULL*DIMF) out[t] = 0.0f;
}

__global__ void k_ugbits(const float* __restrict__ edge){
    int a = blockIdx.x, c = threadIdx.x;
    bool b = edge[a*NFULL + c] != 0.0f;
    unsigned m = __ballot_sync(0xffffffffu, b);
    if ((c & 31) == 0) g_ugbits[a*16 + (c>>5)] = m;
}

__global__ void k_ug2(){
    __shared__ uint32_t row[16];
    int a = blockIdx.x, lane = threadIdx.x;
    if (lane < 16) row[lane] = g_ugbits[a*16 + lane];
    __syncwarp();
    uint32_t acc = 0;
    for (int c = 0; c < NFULL; c++){
        if ((row[c>>5] >> (c&31)) & 1u){
            if (lane < 16) acc |= g_ugbits[c*16 + lane];
        }
    }
    if (lane < 16) g_ug2bits[a*16 + lane] = acc;
}

// sigmoid scores, one warp per node
__global__ void k_scores(const float* __restrict__ feat, const float* __restrict__ wp,
                         const float* __restrict__ bp, int pool){
    int tid = threadIdx.x, lane = tid & 31;
    int a = blockIdx.x*4 + (tid >> 5);
    const float* w = wp + pool*DIMF;
    float v = feat[a*DIMF + lane]*w[lane] + feat[a*DIMF + 32 + lane]*w[32 + lane];
    for (int off = 16; off; off >>= 1) v += __shfl_xor_sync(0xffffffffu, v, off);
    if (lane == 0){
        v += bp[pool];
        g_scores[a] = rcpa(1.0f + ex2a(-1.4426950408889634f * v));
    }
}

// top-k by rank counting + gather (set semantics: EGNN is permutation-equivariant)
__global__ void k_select2(int kcnt, const float* __restrict__ feat, const float* __restrict__ coor){
    __shared__ float ss[NFULL];
    __shared__ int   flag[NFULL];
    __shared__ int   nsel_pad;
    int a = threadIdx.x;
    float s = g_scores[a];
    ss[a] = s;
    __syncthreads();
    int r = 0;
    for (int b = 0; b < NFULL; b++){
        float sb = ss[b];
        r += (sb > s) || (sb == s && b < a);
    }
    int sel = (r < kcnt) ? 1 : 0;
    flag[a] = sel;
    __syncthreads();
    if (sel){
        int pos = 0;
        for (int b = 0; b < a; b++) pos += flag[b];
        g_idx[pos] = a;
    }
    if (a == 0) nsel_pad = kcnt;
    __syncthreads();
    int n = nsel_pad;
    // gather feat*score and coords over selected set
    for (int e = a; e < n*DIMF; e += NFULL){
        int i = e >> 6, t = e & 63;
        int src = g_idx[i];
        g_hc[e] = feat[src*DIMF + t] * g_scores[src];
    }
    for (int e = a; e < n*3; e += NFULL){
        int i = e / 3, t = e - 3*i;
        g_cA[e] = coor[g_idx[i]*3 + t];
    }
}

__global__ void k_gsub(int n){
    int i = blockIdx.x, lane = threadIdx.x;
    int gi = g_idx[i];
    for (int w = 0; w < 16; w++){
        int j = w*32 + lane;
        bool bit = false;
        if (j < n){
            int gj = g_idx[j];
            bit = (g_ug2bits[gi*16 + (gj>>5)] >> (gj&31)) & 1u;
        }
        unsigned m = __ballot_sync(0xffffffffu, bit);
        if (lane == 0) g_gsub[i*16 + w] = m;
    }
}

// A = h@We1[0:64] + be1, B = h@We1[64:128]; also zero m_i and init coor_next
__global__ void k_AB(int n, const float* __restrict__ We1L, const float* __restrict__ be1L, int flag){
    __shared__ float h[DIMF];
    int i = blockIdx.x, tid = threadIdx.x;
    if (tid < DIMF) h[tid] = g_hc[i*DIMF + tid];
    else if (tid < DIMF + MD) g_mi[i*MD + (tid - DIMF)] = 0.0f;
    else if (tid < DIMF + MD + 3){
        int c = tid - DIMF - MD;
        float* cnext = flag ? g_cA : g_cB;
        const float* ccur = flag ? g_cB : g_cA;
        cnext[i*3 + c] = ccur[i*3 + c];
    }
    __syncthreads();
    for (int k = tid; k < H1; k += 256){
        float a = be1L[k], b = 0.0f;
        #pragma unroll
        for (int d = 0; d < DIMF; d++){
            a = fmaf(h[d], We1L[d*H1 + k], a);
            b = fmaf(h[d], We1L[(DIMF + d)*H1 + k], b);
        }
        g_Arow[i*H1 + k] = a;
        g_Brow[i*H1 + k] = b;
    }
}

// ---------------- the heavy edge kernel ----------------
// 128 threads = 4 warps; warp wi handles rows (i0+2wi, i0+2wi+1) sharing lane j.
// All hot FMAs are packed f32x2 (FFMA2).
__global__ void __launch_bounds__(128, 3) k_edge(int n, int flag,
    const float* __restrict__ We1L, const float* __restrict__ We2L,
    const float* __restrict__ be2L, const float* __restrict__ Wc1L,
    const float* __restrict__ bc1L, const float* __restrict__ Wc2L,
    const float* __restrict__ bc2L)
{
    extern __shared__ float sm[];
    float* ws   = sm;               // 260*20 (We2 rows: 17 used + 3 zero pad; 16B-aligned rows)
    float* Bs   = ws + 5200;        // 260*33 (B tile, k-major, +1 pad)
    float* As2  = Bs + 8580;        // 260*8  (A tile, k-major, row pairs)
    float* wde  = As2 + 2080;       // 260*2  (wd,we interleaved)
    float* wc1  = wde + 520;        // 17*68
    float* bc1s = wc1 + 1156;       // 68
    float* wc2s = bc1s + 68;        // 68
    float* be2s = wc2s + 68;        // 20 (17 used + pad)
    float* cj   = be2s + 20;        // 96
    float* bc2s = cj + 96;          // 4 pad  -> total 17792 floats = 71168 B

    int tid = threadIdx.x, lane = tid & 31, wi = tid >> 5;
    const float* ccur = flag ? g_cB : g_cA;
    float* cnext = flag ? g_cA : g_cB;

    const ull NL2E = dup2(-1.4426950408889634f);
    const ull ONE2 = dup2(1.0f);

    for (int t = tid; t < 5200; t += 128){
        int k = t / 20, c = t - 20*k;
        ws[t] = (c < MD) ? We2L[k*MD + c] : 0.0f;
    }
    for (int t = tid; t < H1; t += 128){
        wde[t*2 + 0] = We1L[128*H1 + t];
        wde[t*2 + 1] = We1L[129*H1 + t];
    }
    for (int t = tid; t < MD*CHID; t += 128) wc1[t] = Wc1L[t];
    if (tid < CHID){ bc1s[tid] = bc1L[tid]; wc2s[tid] = Wc2L[tid]; }
    if (tid < 20) be2s[tid] = (tid < MD) ? be2L[tid] : 0.0f;
    if (tid == 0) bc2s[0] = bc2L[0];

    int i0 = blockIdx.x * RPB;
    for (int e = tid; e < RPB*H1; e += 128){
        int r = e / H1, k = e - r*H1;
        int ii = i0 + r;
        As2[k*8 + r] = (ii < n) ? g_Arow[ii*H1 + k] : 0.0f;
    }
    __syncthreads();
    const float bc2v = bc2s[0];

    int ia = i0 + 2*wi, ib = ia + 1;
    bool iv0 = (ia < n), iv1 = (ib < n);
    float c0x=0,c0y=0,c0z=0,c1x=0,c1y=0,c1z=0;
    if (iv0){ c0x=ccur[ia*3]; c0y=ccur[ia*3+1]; c0z=ccur[ia*3+2]; }
    if (iv1){ c1x=ccur[ib*3]; c1y=ccur[ib*3+1]; c1z=ccur[ib*3+2]; }
    const uint32_t* grow0 = g_gsub + ia*16;
    const uint32_t* grow1 = g_gsub + ib*16;

    float macc0[MD], macc1[MD];
    #pragma unroll
    for (int t = 0; t < MD; t++){ macc0[t] = 0.0f; macc1[t] = 0.0f; }
    float cr0x=0,cr0y=0,cr0z=0, cr1x=0,cr1y=0,cr1z=0;

    const ull* be2u = (const ull*)be2s;
    const ull* wc1u = (const ull*)wc1;
    const ull* bc1u = (const ull*)bc1s;

    int nch = (n + 31) >> 5;
    for (int ch = blockIdx.y; ch < nch; ch += NSPL){
        int j0 = ch << 5;
        __syncthreads();
        for (int e = tid; e < 32*H1; e += 128){
            int jj = e / H1, k = e - jj*H1;
            int j = j0 + jj;
            Bs[k*33 + jj] = (j < n) ? g_Brow[j*H1 + k] : 0.0f;
        }
        for (int t = tid; t < 96; t += 128){
            int c = t / 32, jj = t - c*32;
            int j = j0 + jj;
            cj[t] = (j < n) ? ccur[j*3 + c] : 0.0f;
        }
        __syncthreads();
        if (!iv0) continue;   // staging/syncs above run unconditionally

        int j = j0 + lane;
        bool jv = (j < n);
        float jx = cj[lane], jy = cj[32+lane], jz = cj[64+lane];
        float r0x = c0x-jx, r0y = c0y-jy, r0z = c0z-jz;
        float r1x = c1x-jx, r1y = c1y-jy, r1z = c1z-jz;
        float d0 = r0x*r0x + r0y*r0y + r0z*r0z;
        float d1 = r1x*r1x + r1y*r1y + r1z*r1z;
        uint32_t gb0 = grow0[ch];
        uint32_t gb1 = iv1 ? grow1[ch] : 0u;
        ull d01  = pk2(d0, d1);
        ull ge01 = pk2(((gb0 >> lane) & 1u) ? 1.0f : 0.0f,
                       ((gb1 >> lane) & 1u) ? 1.0f : 0.0f);

        ull m2a[9], m2b[9];
        #pragma unroll
        for (int tp = 0; tp < 9; tp++){ m2a[tp] = be2u[tp]; m2b[tp] = m2a[tp]; }

        #pragma unroll 2
        for (int k = 0; k < H1; k++){
            ull ap = *(const ull*)(As2 + k*8 + 2*wi);     // (row a, row b)
            float2 wv = *(const float2*)(wde + 2*k);
            float bsv = Bs[k*33 + lane];
            ull pre = add2(ap, dup2(bsv));                // rows packed
            pre = fma2(d01, dup2(wv.x), pre);
            pre = fma2(ge01, dup2(wv.y), pre);
            ull s2 = silu2(pre, NL2E, ONE2);
            float s0, s1; unpk(s2, s0, s1);
            ull s0d = dup2(s0), s1d = dup2(s1);
            const ull* q = (const ull*)(ws + k*20);       // t-pairs
            #pragma unroll
            for (int tp = 0; tp < 9; tp++){
                ull qv = q[tp];
                m2a[tp] = fma2(s0d, qv, m2a[tp]);
                m2b[tp] = fma2(s1d, qv, m2b[tp]);
            }
        }

        // me = silu(m0)
        float me0[MD+1], me1[MD+1];
        #pragma unroll
        for (int tp = 0; tp < 9; tp++){
            float x0,x1,y0,y1;
            unpk(m2a[tp], x0, x1); unpk(m2b[tp], y0, y1);
            me0[2*tp] = siluf(x0); me1[2*tp] = siluf(y0);
            if (2*tp + 1 < MD){ me0[2*tp+1] = siluf(x1); me1[2*tp+1] = siluf(y1); }
        }

        // cw = silu(me @ Wc1 + bc1) @ Wc2 + bc2, per row, hidden dim packed
        float cw0 = bc2v, cw1 = bc2v;
        #pragma unroll 1
        for (int r = 0; r < 2; r++){
            const float* me = r ? me1 : me0;
            float cw = bc2v;
            #pragma unroll 1
            for (int half = 0; half < 2; half++){
                ull acc[17];
                #pragma unroll
                for (int p = 0; p < 17; p++) acc[p] = bc1u[half*17 + p];
                #pragma unroll 1
                for (int t = 0; t < MD; t++){
                    ull md = dup2(me[t]);
                    const ull* wr = wc1u + t*34 + half*17;
                    #pragma unroll
                    for (int p = 0; p < 17; p++) acc[p] = fma2(md, wr[p], acc[p]);
                }
                #pragma unroll
                for (int p = 0; p < 17; p++){
                    float a0, a1; unpk(acc[p], a0, a1);
                    cw = fmaf(siluf(a0), wc2s[half*34 + 2*p], cw);
                    cw = fmaf(siluf(a1), wc2s[half*34 + 2*p + 1], cw);
                }
            }
            if (r == 0) cw0 = cw; else cw1 = cw;
        }

        if (jv){
            #pragma unroll
            for (int t = 0; t < MD; t++) macc0[t] += me0[t];
            cr0x = fmaf(cw0, r0x, cr0x);
            cr0y = fmaf(cw0, r0y, cr0y);
            cr0z = fmaf(cw0, r0z, cr0z);
            if (iv1){
                #pragma unroll
                for (int t = 0; t < MD; t++) macc1[t] += me1[t];
                cr1x = fmaf(cw1, r1x, cr1x);
                cr1y = fmaf(cw1, r1y, cr1y);
                cr1z = fmaf(cw1, r1z, cr1z);
            }
        }
    }

    if (iv0){
        #pragma unroll
        for (int t = 0; t < MD; t++){
            float v = macc0[t];
            for (int off = 16; off; off >>= 1) v += __shfl_xor_sync(0xffffffffu, v, off);
            if (lane == 0) atomicAdd(&g_mi[ia*MD + t], v);
        }
        float v;
        v = cr0x; for (int off = 16; off; off >>= 1) v += __shfl_xor_sync(0xffffffffu, v, off);
        if (lane == 0) atomicAdd(&cnext[ia*3 + 0], v);
        v = cr0y; for (int off = 16; off; off >>= 1) v += __shfl_xor_sync(0xffffffffu, v, off);
        if (lane == 0) atomicAdd(&cnext[ia*3 + 1], v);
        v = cr0z; for (int off = 16; off; off >>= 1) v += __shfl_xor_sync(0xffffffffu, v, off);
        if (lane == 0) atomicAdd(&cnext[ia*3 + 2], v);
    }
    if (iv1){
        #pragma unroll
        for (int t = 0; t < MD; t++){
            float v = macc1[t];
            for (int off = 16; off; off >>= 1) v += __shfl_xor_sync(0xffffffffu, v, off);
            if (lane == 0) atomicAdd(&g_mi[ib*MD + t], v);
        }
        float v;
        v = cr1x; for (int off = 16; off; off >>= 1) v += __shfl_xor_sync(0xffffffffu, v, off);
        if (lane == 0) atomicAdd(&cnext[ib*3 + 0], v);
        v = cr1y; for (int off = 16; off; off >>= 1) v += __shfl_xor_sync(0xffffffffu, v, off);
        if (lane == 0) atomicAdd(&cnext[ib*3 + 1], v);
        v = cr1z; for (int off = 16; off; off >>= 1) v += __shfl_xor_sync(0xffffffffu, v, off);
        if (lane == 0) atomicAdd(&cnext[ib*3 + 2], v);
    }
}

// node MLP + double residual + relu: hc = relu(2*hc + MLP([hc, m_i]))
__global__ void k_node(int n, const float* __restrict__ Wn1L, const float* __restrict__ bn1L,
                       const float* __restrict__ Wn2L, const float* __restrict__ bn2L){
    __shared__ float in[81];
    __shared__ float z[128];
    int i = blockIdx.x, tid = threadIdx.x;
    if (tid < DIMF) in[tid] = g_hc[i*DIMF + tid];
    else if (tid < 81) in[tid] = g_mi[i*MD + (tid - DIMF)];
    __syncthreads();
    float acc = bn1L[tid];
    #pragma unroll 1
    for (int k = 0; k < 81; k++) acc = fmaf(in[k], Wn1L[k*128 + tid], acc);
    z[tid] = siluf(acc);
    __syncthreads();
    if (tid < DIMF){
        float a2 = bn2L[tid];
        #pragma unroll 1
        for (int k = 0; k < 128; k++) a2 = fmaf(z[k], Wn2L[k*DIMF + tid], a2);
        float v = 2.0f*in[tid] + a2;
        g_hc[i*DIMF + tid] = fmaxf(v, 0.0f);
    }
}

__global__ void k_scatter(float* out){
    int i = blockIdx.x, t = threadIdx.x;
    int a = g_idx[i];
    float v = g_hc[i*DIMF + t];
    float* o = &out[a*DIMF + t];
    *o = fmaxf(*o, v);
}

// ---------------- host ----------------
extern "C" void kernel_launch(void* const* d_in, const int* in_sizes, int n_in,
                              void* d_out, int out_size){
    const float* feat = (const float*)d_in[0];
    const float* coor = (const float*)d_in[1];
    const float* edge = (const float*)d_in[2];
    const float* We1  = (const float*)d_in[3];
    const float* be1  = (const float*)d_in[4];
    const float* We2  = (const float*)d_in[5];
    const float* be2  = (const float*)d_in[6];
    const float* Wc1  = (const float*)d_in[7];
    const float* bc1  = (const float*)d_in[8];
    const float* Wc2  = (const float*)d_in[9];
    const float* bc2  = (const float*)d_in[10];
    const float* Wn1  = (const float*)d_in[11];
    const float* bn1  = (const float*)d_in[12];
    const float* Wn2  = (const float*)d_in[13];
    const float* bn2  = (const float*)d_in[14];
    const float* wp   = (const float*)d_in[15];
    const float* bp   = (const float*)d_in[16];
    float* out = (float*)d_out;

    static const int KC[3] = {460, 358, 307};
    const int EDGE_SMEM = 17792 * 4;          // 71168 B
    cudaFuncSetAttribute(k_edge, cudaFuncAttributeMaxDynamicSharedMemorySize, EDGE_SMEM);

    k_zero_out<<<128, 256>>>(out);
    k_ugbits<<<512, 512>>>(edge);
    k_ug2<<<512, 32>>>();

    for (int p = 0; p < 3; p++){
        int n = KC[p];
        k_scores<<<128, 128>>>(feat, wp, bp, p);
        k_select2<<<1, 512>>>(n, feat, coor);
        k_gsub<<<n, 32>>>(n);
        for (int l = 0; l < 3; l++){
            k_AB<<<n, 256>>>(n, We1 + l*130*H1, be1 + l*H1, l & 1);
            dim3 ge((n + RPB - 1) / RPB, NSPL);
            k_edge<<<ge, 128, EDGE_SMEM>>>(n, l & 1,
                We1 + l*130*H1, We2 + l*H1*MD, be2 + l*MD,
                Wc1 + l*MD*CHID, bc1 + l*CHID, Wc2 + l*CHID, bc2 + l);
            k_node<<<n, 128>>>(n, Wn1 + l*81*128, bn1 + l*128, Wn2 + l*128*DIMF, bn2 + l*DIMF);
        }
        k_scatter<<<n, 64>>>(out);
    }
}

// round 4
// speedup vs baseline: 1.0435x; 1.0435x over previous
#include <cuda_runtime.h>
#include <stdint.h>

#define NFULL 512
#define DIMF  64
#define H1    260   // 2*EIN
#define MD    17
#define CHID  68
#define NMAX  460
#define RPB   16    // rows per block (4 warps x 4 rows)

// ---------------- device scratch ----------------
__device__ uint32_t g_ugbits[NFULL*16];
__device__ uint32_t g_ug2bits[NFULL*16];
__device__ float    g_scores[NFULL];
__device__ int      g_idx[NFULL];
__device__ uint32_t g_gsub[NMAX*16];
__device__ float    g_hc[NMAX*DIMF];
__device__ float    g_cA[NMAX*3];
__device__ float    g_cB[NMAX*3];
__device__ float    g_Arow[NMAX*H1];
__device__ float    g_Brow[NMAX*H1];
__device__ float    g_mi[NMAX*MD];

__device__ __forceinline__ float ex2a(float x){ float y; asm("ex2.approx.ftz.f32 %0, %1;" : "=f"(y) : "f"(x)); return y; }
__device__ __forceinline__ float rcpa(float x){ float y; asm("rcp.approx.ftz.f32 %0, %1;" : "=f"(y) : "f"(x)); return y; }
__device__ __forceinline__ float siluf(float x){
    return x * rcpa(1.0f + ex2a(-1.4426950408889634f * x));
}

// ---------------- misc kernels ----------------
__global__ void k_zero_out(float* out){
    int t = blockIdx.x*blockDim.x + threadIdx.x;
    if (t < NFULL*DIMF) out[t] = 0.0f;
}

__global__ void k_ugbits(const float* __restrict__ edge){
    int a = blockIdx.x, c = threadIdx.x;
    bool b = edge[a*NFULL + c] != 0.0f;
    unsigned m = __ballot_sync(0xffffffffu, b);
    if ((c & 31) == 0) g_ugbits[a*16 + (c>>5)] = m;
}

__global__ void k_ug2(){
    __shared__ uint32_t row[16];
    int a = blockIdx.x, lane = threadIdx.x;
    if (lane < 16) row[lane] = g_ugbits[a*16 + lane];
    __syncwarp();
    uint32_t acc = 0;
    for (int c = 0; c < NFULL; c++){
        if ((row[c>>5] >> (c&31)) & 1u){
            if (lane < 16) acc |= g_ugbits[c*16 + lane];
        }
    }
    if (lane < 16) g_ug2bits[a*16 + lane] = acc;
}

__global__ void k_scores(const float* __restrict__ feat, const float* __restrict__ wp,
                         const float* __restrict__ bp, int pool){
    int tid = threadIdx.x, lane = tid & 31;
    int a = blockIdx.x*4 + (tid >> 5);
    const float* w = wp + pool*DIMF;
    float v = feat[a*DIMF + lane]*w[lane] + feat[a*DIMF + 32 + lane]*w[32 + lane];
    for (int off = 16; off; off >>= 1) v += __shfl_xor_sync(0xffffffffu, v, off);
    if (lane == 0){
        v += bp[pool];
        g_scores[a] = rcpa(1.0f + ex2a(-1.4426950408889634f * v));
    }
}

// top-k by rank counting + gather (set semantics; EGNN is permutation-equivariant)
__global__ void k_select2(int kcnt, const float* __restrict__ feat, const float* __restrict__ coor){
    __shared__ float ss[NFULL];
    __shared__ int   flag[NFULL];
    int a = threadIdx.x;
    float s = g_scores[a];
    ss[a] = s;
    __syncthreads();
    int r = 0;
    for (int b = 0; b < NFULL; b++){
        float sb = ss[b];
        r += (sb > s) || (sb == s && b < a);
    }
    int sel = (r < kcnt) ? 1 : 0;
    flag[a] = sel;
    __syncthreads();
    if (sel){
        int pos = 0;
        for (int b = 0; b < a; b++) pos += flag[b];
        g_idx[pos] = a;
    }
    __syncthreads();
    int n = kcnt;
    for (int e = a; e < n*DIMF; e += NFULL){
        int i = e >> 6, t = e & 63;
        int src = g_idx[i];
        g_hc[e] = feat[src*DIMF + t] * g_scores[src];
    }
    for (int e = a; e < n*3; e += NFULL){
        int i = e / 3, t = e - 3*i;
        g_cA[e] = coor[g_idx[i]*3 + t];
    }
}

__global__ void k_gsub(int n){
    int i = blockIdx.x, lane = threadIdx.x;
    int gi = g_idx[i];
    for (int w = 0; w < 16; w++){
        int j = w*32 + lane;
        bool bit = false;
        if (j < n){
            int gj = g_idx[j];
            bit = (g_ug2bits[gi*16 + (gj>>5)] >> (gj&31)) & 1u;
        }
        unsigned m = __ballot_sync(0xffffffffu, bit);
        if (lane == 0) g_gsub[i*16 + w] = m;
    }
}

// A = h@We1[0:64] + be1, B = h@We1[64:128]; also zero m_i and init coor_next
__global__ void k_AB(int n, const float* __restrict__ We1L, const float* __restrict__ be1L, int flag){
    __shared__ float h[DIMF];
    int i = blockIdx.x, tid = threadIdx.x;
    if (tid < DIMF) h[tid] = g_hc[i*DIMF + tid];
    else if (tid < DIMF + MD) g_mi[i*MD + (tid - DIMF)] = 0.0f;
    else if (tid < DIMF + MD + 3){
        int c = tid - DIMF - MD;
        float* cnext = flag ? g_cA : g_cB;
        const float* ccur = flag ? g_cB : g_cA;
        cnext[i*3 + c] = ccur[i*3 + c];
    }
    __syncthreads();
    for (int k = tid; k < H1; k += 256){
        float a = be1L[k], b = 0.0f;
        #pragma unroll
        for (int d = 0; d < DIMF; d++){
            a = fmaf(h[d], We1L[d*H1 + k], a);
            b = fmaf(h[d], We1L[(DIMF + d)*H1 + k], b);
        }
        g_Arow[i*H1 + k] = a;
        g_Brow[i*H1 + k] = b;
    }
}

// ---------------- the heavy edge kernel ----------------
// 128 threads = 4 warps; warp wi handles rows i0+4wi .. i0+4wi+3 sharing lane j.
__global__ void __launch_bounds__(128) k_edge(int n, int flag,
    const float* __restrict__ We1L, const float* __restrict__ We2L,
    const float* __restrict__ be2L, const float* __restrict__ Wc1L,
    const float* __restrict__ bc1L, const float* __restrict__ Wc2L,
    const float* __restrict__ bc2L)
{
    extern __shared__ float sm[];
    float* ws   = sm;               // 260*20 (We2 rows: 17 used + 3 pad, 16B-aligned)
    float* Bs   = ws + 5200;        // 260*32 (B tile, k-major, stride 32 conflict-free)
    float* As2  = Bs + 8320;        // 260*16 (A tile, k-major, 4-row groups, float4)
    float* wde  = As2 + 4160;       // 260*2  (wd,we interleaved)
    float* wc1  = wde + 520;        // 17*68  (float4 as [t][17 x float4])
    float* bc1s = wc1 + 1156;       // 68
    float* wc2s = bc1s + 68;        // 68
    float* be2s = wc2s + 68;        // 20 (17 used)
    float* cj   = be2s + 20;        // 96
    float* bc2s = cj + 96;          // 4 pad -> total 19612 floats = 78448 B

    int tid = threadIdx.x, lane = tid & 31, wi = tid >> 5;
    const float* ccur = flag ? g_cB : g_cA;
    float* cnext = flag ? g_cA : g_cB;

    for (int t = tid; t < 5200; t += 128){
        int k = t / 20, c = t - 20*k;
        ws[t] = (c < MD) ? We2L[k*MD + c] : 0.0f;
    }
    for (int t = tid; t < H1; t += 128){
        wde[t*2 + 0] = We1L[128*H1 + t];
        wde[t*2 + 1] = We1L[129*H1 + t];
    }
    for (int t = tid; t < MD*CHID; t += 128) wc1[t] = Wc1L[t];
    if (tid < CHID){ bc1s[tid] = bc1L[tid]; wc2s[tid] = Wc2L[tid]; }
    if (tid < 20) be2s[tid] = (tid < MD) ? be2L[tid] : 0.0f;
    if (tid == 0) bc2s[0] = bc2L[0];

    int i0 = blockIdx.x * RPB;
    for (int e = tid; e < RPB*H1; e += 128){
        int r = e / H1, k = e - r*H1;
        int ii = i0 + r;
        As2[k*16 + r] = (ii < n) ? g_Arow[ii*H1 + k] : 0.0f;
    }
    __syncthreads();
    const float bc2v = bc2s[0];

    int ia = i0 + 4*wi;
    bool iv[4];
    float cx[4], cy[4], cz[4];
    uint32_t growbase = ia*16;
    #pragma unroll
    for (int r = 0; r < 4; r++){
        int row = ia + r;
        iv[r] = (row < n);
        cx[r] = iv[r] ? ccur[row*3+0] : 0.0f;
        cy[r] = iv[r] ? ccur[row*3+1] : 0.0f;
        cz[r] = iv[r] ? ccur[row*3+2] : 0.0f;
    }

    const float4* wc14 = (const float4*)wc1;
    const float4* bc14 = (const float4*)bc1s;
    const float4* wc24 = (const float4*)wc2s;

    int nch = (n + 31) >> 5;
    for (int ch = blockIdx.y; ch < nch; ch += gridDim.y){
        int j0 = ch << 5;
        __syncthreads();
        for (int e = tid; e < 32*H1; e += 128){
            int jj = e / H1, k = e - jj*H1;
            int j = j0 + jj;
            Bs[(k<<5) + jj] = (j < n) ? g_Brow[j*H1 + k] : 0.0f;
        }
        for (int t = tid; t < 96; t += 128){
            int c = t / 32, jj = t - c*32;
            int j = j0 + jj;
            cj[t] = (j < n) ? ccur[j*3 + c] : 0.0f;
        }
        __syncthreads();
        if (!iv[0]) continue;   // staging/syncs above run unconditionally

        int j = j0 + lane;
        bool jv = (j < n);
        float jx = cj[lane], jy = cj[32+lane], jz = cj[64+lane];

        float rx[4], ry[4], rz[4], dd[4], ge[4];
        #pragma unroll
        for (int r = 0; r < 4; r++){
            rx[r] = cx[r]-jx; ry[r] = cy[r]-jy; rz[r] = cz[r]-jz;
            dd[r] = rx[r]*rx[r] + ry[r]*ry[r] + rz[r]*rz[r];
            uint32_t gb = iv[r] ? g_gsub[growbase + r*16 + ch] : 0u;
            ge[r] = ((gb >> lane) & 1u) ? 1.0f : 0.0f;
        }

        float m0[MD], m1[MD], m2[MD], m3[MD];
        #pragma unroll
        for (int t = 0; t < MD; t++){
            float b = be2s[t];
            m0[t] = b; m1[t] = b; m2[t] = b; m3[t] = b;
        }

        #pragma unroll 2
        for (int k = 0; k < H1; k++){
            float4 ap = *(const float4*)(As2 + (k<<4) + 4*wi);
            float2 wv = *(const float2*)(wde + 2*k);
            float bsv = Bs[(k<<5) + lane];
            float p0 = ap.x + bsv; p0 = fmaf(dd[0], wv.x, p0); p0 = fmaf(ge[0], wv.y, p0);
            float p1 = ap.y + bsv; p1 = fmaf(dd[1], wv.x, p1); p1 = fmaf(ge[1], wv.y, p1);
            float p2 = ap.z + bsv; p2 = fmaf(dd[2], wv.x, p2); p2 = fmaf(ge[2], wv.y, p2);
            float p3 = ap.w + bsv; p3 = fmaf(dd[3], wv.x, p3); p3 = fmaf(ge[3], wv.y, p3);
            float s0 = siluf(p0), s1 = siluf(p1), s2 = siluf(p2), s3 = siluf(p3);
            float qv[MD];
            *(float4*)(qv+0)  = ((const float4*)(ws + k*20))[0];
            *(float4*)(qv+4)  = ((const float4*)(ws + k*20))[1];
            *(float4*)(qv+8)  = ((const float4*)(ws + k*20))[2];
            *(float4*)(qv+12) = ((const float4*)(ws + k*20))[3];
            qv[16] = ws[k*20 + 16];
            #pragma unroll
            for (int t = 0; t < MD; t++){
                m0[t] = fmaf(s0, qv[t], m0[t]);
                m1[t] = fmaf(s1, qv[t], m1[t]);
                m2[t] = fmaf(s2, qv[t], m2[t]);
                m3[t] = fmaf(s3, qv[t], m3[t]);
            }
        }

        // me = silu(m0) in place (constant indices -> registers)
        #pragma unroll
        for (int t = 0; t < MD; t++){
            m0[t] = siluf(m0[t]);
            m1[t] = siluf(m1[t]);
            m2[t] = siluf(m2[t]);
            m3[t] = siluf(m3[t]);
        }

        // cw_r = silu(me_r @ Wc1 + bc1) @ Wc2 + bc2
        // hidden dim rolled (p4), t fully unrolled so me stays in registers.
        float cw[4];
        #pragma unroll 1
        for (int rr = 0; rr < 4; rr++){
            const float* me = (rr==0)?m0:(rr==1)?m1:(rr==2)?m2:m3;
            float c = bc2v;
            #pragma unroll 1
            for (int p4 = 0; p4 < CHID/4; p4++){
                float4 acc = bc14[p4];
                #pragma unroll
                for (int t = 0; t < MD; t++){
                    float4 wv = wc14[t*(CHID/4) + p4];
                    float md = me[t];     // constant index under unroll
                    acc.x = fmaf(md, wv.x, acc.x);
                    acc.y = fmaf(md, wv.y, acc.y);
                    acc.z = fmaf(md, wv.z, acc.z);
                    acc.w = fmaf(md, wv.w, acc.w);
                }
                float4 w2 = wc24[p4];
                c = fmaf(siluf(acc.x), w2.x, c);
                c = fmaf(siluf(acc.y), w2.y, c);
                c = fmaf(siluf(acc.z), w2.z, c);
                c = fmaf(siluf(acc.w), w2.w, c);
            }
            cw[rr] = c;
        }

        // per-chunk masked reduction + atomics
        float mask = jv ? 1.0f : 0.0f;
        #pragma unroll 1
        for (int rr = 0; rr < 4; rr++){
            int row = ia + rr;
            if (row >= n) break;
            const float* me = (rr==0)?m0:(rr==1)?m1:(rr==2)?m2:m3;
            #pragma unroll
            for (int t = 0; t < MD; t++){
                float v = me[t] * mask;
                for (int off = 16; off; off >>= 1) v += __shfl_xor_sync(0xffffffffu, v, off);
                if (lane == 0) atomicAdd(&g_mi[row*MD + t], v);
            }
            float vx = cw[rr]*rx[rr]*mask;
            float vy = cw[rr]*ry[rr]*mask;
            float vz = cw[rr]*rz[rr]*mask;
            for (int off = 16; off; off >>= 1){
                vx += __shfl_xor_sync(0xffffffffu, vx, off);
                vy += __shfl_xor_sync(0xffffffffu, vy, off);
                vz += __shfl_xor_sync(0xffffffffu, vz, off);
            }
            if (lane == 0){
                atomicAdd(&cnext[row*3 + 0], vx);
                atomicAdd(&cnext[row*3 + 1], vy);
                atomicAdd(&cnext[row*3 + 2], vz);
            }
        }
    }
}

// node MLP + double residual + relu: hc = relu(2*hc + MLP([hc, m_i]))
__global__ void k_node(int n, const float* __restrict__ Wn1L, const float* __restrict__ bn1L,
                       const float* __restrict__ Wn2L, const float* __restrict__ bn2L){
    __shared__ float in[81];
    __shared__ float z[128];
    int i = blockIdx.x, tid = threadIdx.x;
    if (tid < DIMF) in[tid] = g_hc[i*DIMF + tid];
    else if (tid < 81) in[tid] = g_mi[i*MD + (tid - DIMF)];
    __syncthreads();
    float acc = bn1L[tid];
    #pragma unroll 1
    for (int k = 0; k < 81; k++) acc = fmaf(in[k], Wn1L[k*128 + tid], acc);
    z[tid] = siluf(acc);
    __syncthreads();
    if (tid < DIMF){
        float a2 = bn2L[tid];
        #pragma unroll 1
        for (int k = 0; k < 128; k++) a2 = fmaf(z[k], Wn2L[k*DIMF + tid], a2);
        float v = 2.0f*in[tid] + a2;
        g_hc[i*DIMF + tid] = fmaxf(v, 0.0f);
    }
}

__global__ void k_scatter(float* out){
    int i = blockIdx.x, t = threadIdx.x;
    int a = g_idx[i];
    float v = g_hc[i*DIMF + t];
    float* o = &out[a*DIMF + t];
    *o = fmaxf(*o, v);
}

// ---------------- host ----------------
extern "C" void kernel_launch(void* const* d_in, const int* in_sizes, int n_in,
                              void* d_out, int out_size){
    const float* feat = (const float*)d_in[0];
    const float* coor = (const float*)d_in[1];
    const float* edge = (const float*)d_in[2];
    const float* We1  = (const float*)d_in[3];
    const float* be1  = (const float*)d_in[4];
    const float* We2  = (const float*)d_in[5];
    const float* be2  = (const float*)d_in[6];
    const float* Wc1  = (const float*)d_in[7];
    const float* bc1  = (const float*)d_in[8];
    const float* Wc2  = (const float*)d_in[9];
    const float* bc2  = (const float*)d_in[10];
    const float* Wn1  = (const float*)d_in[11];
    const float* bn1  = (const float*)d_in[12];
    const float* Wn2  = (const float*)d_in[13];
    const float* bn2  = (const float*)d_in[14];
    const float* wp   = (const float*)d_in[15];
    const float* bp   = (const float*)d_in[16];
    float* out = (float*)d_out;

    static const int KC[3] = {460, 358, 307};
    const int EDGE_SMEM = 19612 * 4;          // 78448 B
    cudaFuncSetAttribute(k_edge, cudaFuncAttributeMaxDynamicSharedMemorySize, EDGE_SMEM);

    k_zero_out<<<128, 256>>>(out);
    k_ugbits<<<512, 512>>>(edge);
    k_ug2<<<512, 32>>>();

    for (int p = 0; p < 3; p++){
        int n = KC[p];
        int nch = (n + 31) >> 5;
        k_scores<<<128, 128>>>(feat, wp, bp, p);
        k_select2<<<1, 512>>>(n, feat, coor);
        k_gsub<<<n, 32>>>(n);
        for (int l = 0; l < 3; l++){
            k_AB<<<n, 256>>>(n, We1 + l*130*H1, be1 + l*H1, l & 1);
            dim3 ge((n + RPB - 1) / RPB, nch);
            k_edge<<<ge, 128, EDGE_SMEM>>>(n, l & 1,
                We1 + l*130*H1, We2 + l*H1*MD, be2 + l*MD,
                Wc1 + l*MD*CHID, bc1 + l*CHID, Wc2 + l*CHID, bc2 + l);
            k_node<<<n, 128>>>(n, Wn1 + l*81*128, bn1 + l*128, Wn2 + l*128*DIMF, bn2 + l*DIMF);
        }
        k_scatter<<<n, 64>>>(out);
    }
}

// round 5
// speedup vs baseline: 1.1477x; 1.0998x over previous
#include <cuda_runtime.h>
#include <stdint.h>

#define NFULL 512
#define DIMF  64
#define H1    260   // 2*EIN
#define MD    17
#define CHID  68
#define NMAX  460
#define RPB   16    // rows per block (8 warps x 2 rows)

typedef unsigned long long ull;

// ---------------- device scratch ----------------
__device__ uint32_t g_ugbits[NFULL*16];
__device__ uint32_t g_ug2bits[NFULL*16];
__device__ float    g_scores[NFULL];
__device__ int      g_idx[NFULL];
__device__ uint32_t g_gsub[NMAX*16];
__device__ float    g_hc[NMAX*DIMF];
__device__ float    g_cA[NMAX*3];
__device__ float    g_cB[NMAX*3];
__device__ float    g_Arow[NMAX*H1];
__device__ float    g_Brow[NMAX*H1];
__device__ float    g_mi[NMAX*MD];

// ---------------- helpers ----------------
__device__ __forceinline__ float ex2a(float x){ float y; asm("ex2.approx.ftz.f32 %0, %1;" : "=f"(y) : "f"(x)); return y; }
__device__ __forceinline__ float rcpa(float x){ float y; asm("rcp.approx.ftz.f32 %0, %1;" : "=f"(y) : "f"(x)); return y; }
__device__ __forceinline__ float siluf(float x){
    return x * rcpa(1.0f + ex2a(-1.4426950408889634f * x));
}
__device__ __forceinline__ ull dup2(float v){
    ull r; asm("mov.b64 %0, {%1,%1};" : "=l"(r) : "r"(__float_as_uint(v))); return r;
}
__device__ __forceinline__ void unpk(ull v, float& lo, float& hi){
    unsigned a, b;
    asm("mov.b64 {%0,%1}, %2;" : "=r"(a), "=r"(b) : "l"(v));
    lo = __uint_as_float(a); hi = __uint_as_float(b);
}
__device__ __forceinline__ ull fma2(ull a, ull b, ull c){
    ull d; asm("fma.rn.f32x2 %0, %1, %2, %3;" : "=l"(d) : "l"(a), "l"(b), "l"(c)); return d;
}

// ---------------- misc kernels ----------------
__global__ void k_zero_out(float* out){
    int t = blockIdx.x*blockDim.x + threadIdx.x;
    if (t < NFULL*DIMF) out[t] = 0.0f;
}

__global__ void k_ugbits(const float* __restrict__ edge){
    int a = blockIdx.x, c = threadIdx.x;
    bool b = edge[a*NFULL + c] != 0.0f;
    unsigned m = __ballot_sync(0xffffffffu, b);
    if ((c & 31) == 0) g_ugbits[a*16 + (c>>5)] = m;
}

__global__ void k_ug2(){
    __shared__ uint32_t row[16];
    int a = blockIdx.x, lane = threadIdx.x;
    if (lane < 16) row[lane] = g_ugbits[a*16 + lane];
    __syncwarp();
    uint32_t acc = 0;
    for (int c = 0; c < NFULL; c++){
        if ((row[c>>5] >> (c&31)) & 1u){
            if (lane < 16) acc |= g_ugbits[c*16 + lane];
        }
    }
    if (lane < 16) g_ug2bits[a*16 + lane] = acc;
}

// scores + top-k by rank counting + gather (set semantics; EGNN is permutation-equivariant)
__global__ void k_select2(int kcnt, const float* __restrict__ feat, const float* __restrict__ coor,
                          const float* __restrict__ wp, const float* __restrict__ bp, int pool){
    __shared__ float ss[NFULL];
    __shared__ int   flag[NFULL];
    int a = threadIdx.x;
    int lane = a & 31, wid = a >> 5;   // 16 warps
    const float* w = wp + pool*DIMF;
    float bpv = bp[pool];
    for (int node = wid; node < NFULL; node += 16){
        float v = feat[node*DIMF + lane]*w[lane] + feat[node*DIMF + 32 + lane]*w[32 + lane];
        for (int off = 16; off; off >>= 1) v += __shfl_xor_sync(0xffffffffu, v, off);
        if (lane == 0){
            float s = rcpa(1.0f + ex2a(-1.4426950408889634f * (v + bpv)));
            ss[node] = s;
            g_scores[node] = s;
        }
    }
    __syncthreads();
    float s = ss[a];
    int r = 0;
    for (int b = 0; b < NFULL; b++){
        float sb = ss[b];
        r += (sb > s) || (sb == s && b < a);
    }
    int sel = (r < kcnt) ? 1 : 0;
    flag[a] = sel;
    __syncthreads();
    if (sel){
        int pos = 0;
        for (int b = 0; b < a; b++) pos += flag[b];
        g_idx[pos] = a;
    }
    __syncthreads();
    int n = kcnt;
    for (int e = a; e < n*DIMF; e += NFULL){
        int i = e >> 6, t = e & 63;
        int src = g_idx[i];
        g_hc[e] = feat[src*DIMF + t] * g_scores[src];
    }
    for (int e = a; e < n*3; e += NFULL){
        int i = e / 3, t = e - 3*i;
        g_cA[e] = coor[g_idx[i]*3 + t];
    }
}

__global__ void k_gsub(int n){
    int i = blockIdx.x, lane = threadIdx.x;
    int gi = g_idx[i];
    for (int w = 0; w < 16; w++){
        int j = w*32 + lane;
        bool bit = false;
        if (j < n){
            int gj = g_idx[j];
            bit = (g_ug2bits[gi*16 + (gj>>5)] >> (gj&31)) & 1u;
        }
        unsigned m = __ballot_sync(0xffffffffu, bit);
        if (lane == 0) g_gsub[i*16 + w] = m;
    }
}

// A = h@We1[0:64] + be1, B = h@We1[64:128]; also zero m_i and init coor_next (layer 0 prep)
__global__ void k_AB(int n, const float* __restrict__ We1L, const float* __restrict__ be1L, int flag){
    __shared__ float h[DIMF];
    int i = blockIdx.x, tid = threadIdx.x;
    if (tid < DIMF) h[tid] = g_hc[i*DIMF + tid];
    else if (tid < DIMF + MD) g_mi[i*MD + (tid - DIMF)] = 0.0f;
    else if (tid < DIMF + MD + 3){
        int c = tid - DIMF - MD;
        float* cnext = flag ? g_cA : g_cB;
        const float* ccur = flag ? g_cB : g_cA;
        cnext[i*3 + c] = ccur[i*3 + c];
    }
    __syncthreads();
    for (int k = tid; k < H1; k += 256){
        float a = be1L[k], b = 0.0f;
        #pragma unroll
        for (int d = 0; d < DIMF; d++){
            a = fmaf(h[d], We1L[d*H1 + k], a);
            b = fmaf(h[d], We1L[(DIMF + d)*H1 + k], b);
        }
        g_Arow[i*H1 + k] = a;
        g_Brow[i*H1 + k] = b;
    }
}

// ---------------- edge epilogue helpers (forceinline, constant indexing) ----------------
__device__ __forceinline__ float coor_mlp(const float (&me)[MD],
        const float4* __restrict__ wc14, const float4* __restrict__ bc14,
        const float4* __restrict__ wc24, float bc2v){
    float c = bc2v;
    #pragma unroll 1
    for (int p4 = 0; p4 < CHID/4; p4++){
        float4 acc = bc14[p4];
        #pragma unroll
        for (int t = 0; t < MD; t++){
            float4 wv = wc14[t*(CHID/4) + p4];
            acc.x = fmaf(me[t], wv.x, acc.x);
            acc.y = fmaf(me[t], wv.y, acc.y);
            acc.z = fmaf(me[t], wv.z, acc.z);
            acc.w = fmaf(me[t], wv.w, acc.w);
        }
        float4 w2 = wc24[p4];
        c = fmaf(siluf(acc.x), w2.x, c);
        c = fmaf(siluf(acc.y), w2.y, c);
        c = fmaf(siluf(acc.z), w2.z, c);
        c = fmaf(siluf(acc.w), w2.w, c);
    }
    return c;
}

__device__ __forceinline__ void reduce_row(int row, const float (&me)[MD], float cwv,
        float rx, float ry, float rz, float mask, int lane, float* __restrict__ cnext){
    #pragma unroll
    for (int t = 0; t < MD; t++){
        float v = me[t] * mask;
        for (int off = 16; off; off >>= 1) v += __shfl_xor_sync(0xffffffffu, v, off);
        if (lane == 0) atomicAdd(&g_mi[row*MD + t], v);
    }
    float vx = cwv*rx*mask, vy = cwv*ry*mask, vz = cwv*rz*mask;
    for (int off = 16; off; off >>= 1){
        vx += __shfl_xor_sync(0xffffffffu, vx, off);
        vy += __shfl_xor_sync(0xffffffffu, vy, off);
        vz += __shfl_xor_sync(0xffffffffu, vz, off);
    }
    if (lane == 0){
        atomicAdd(&cnext[row*3 + 0], vx);
        atomicAdd(&cnext[row*3 + 1], vy);
        atomicAdd(&cnext[row*3 + 2], vz);
    }
}

// ---------------- the heavy edge kernel ----------------
// 256 threads = 8 warps; warp wi handles rows (i0+2wi, i0+2wi+1) sharing lane j.
__global__ void __launch_bounds__(256, 2) k_edge(int n, int flag,
    const float* __restrict__ We1L, const float* __restrict__ We2L,
    const float* __restrict__ be2L, const float* __restrict__ Wc1L,
    const float* __restrict__ bc1L, const float* __restrict__ Wc2L,
    const float* __restrict__ bc2L)
{
    extern __shared__ float sm[];
    float* ws   = sm;               // 260*20 (We2 rows: 17 used + 3 zero pad, 8B-pairable)
    float* Bs   = ws + 5200;        // 260*32 (B tile, k-major, conflict-free)
    float* As2  = Bs + 8320;        // 260*16 (A tile, k-major, 16 rows)
    float* wde  = As2 + 4160;       // 260*2  (wd,we interleaved)
    float* wc1  = wde + 520;        // 17*68
    float* bc1s = wc1 + 1156;       // 68
    float* wc2s = bc1s + 68;        // 68
    float* be2s = wc2s + 68;        // 20 (17 used)
    float* cj   = be2s + 20;        // 96
    float* bc2s = cj + 96;          // 4 pad -> total 19612 floats = 78448 B

    int tid = threadIdx.x, lane = tid & 31, wi = tid >> 5;
    const float* ccur = flag ? g_cB : g_cA;
    float* cnext = flag ? g_cA : g_cB;

    for (int t = tid; t < 5200; t += 256){
        int k = t / 20, c = t - 20*k;
        ws[t] = (c < MD) ? We2L[k*MD + c] : 0.0f;
    }
    for (int t = tid; t < H1; t += 256){
        wde[t*2 + 0] = We1L[128*H1 + t];
        wde[t*2 + 1] = We1L[129*H1 + t];
    }
    for (int t = tid; t < MD*CHID; t += 256) wc1[t] = Wc1L[t];
    if (tid < CHID){ bc1s[tid] = bc1L[tid]; wc2s[tid] = Wc2L[tid]; }
    if (tid < 20) be2s[tid] = (tid < MD) ? be2L[tid] : 0.0f;
    if (tid == 0) bc2s[0] = bc2L[0];

    int i0 = blockIdx.x * RPB;
    for (int e = tid; e < RPB*H1; e += 256){
        int r = e / H1, k = e - r*H1;
        int ii = i0 + r;
        As2[(k<<4) + r] = (ii < n) ? g_Arow[ii*H1 + k] : 0.0f;
    }
    __syncthreads();
    const float bc2v = bc2s[0];

    int ia = i0 + 2*wi, ib = ia + 1;
    bool iv0 = (ia < n), iv1 = (ib < n);
    float c0x=0,c0y=0,c0z=0,c1x=0,c1y=0,c1z=0;
    if (iv0){ c0x=ccur[ia*3]; c0y=ccur[ia*3+1]; c0z=ccur[ia*3+2]; }
    if (iv1){ c1x=ccur[ib*3]; c1y=ccur[ib*3+1]; c1z=ccur[ib*3+2]; }
    const uint32_t* grow0 = g_gsub + ia*16;
    const uint32_t* grow1 = g_gsub + ib*16;

    const float4* wc14 = (const float4*)wc1;
    const float4* bc14 = (const float4*)bc1s;
    const float4* wc24 = (const float4*)wc2s;
    const ull* be2u = (const ull*)be2s;

    int nch = (n + 31) >> 5;
    for (int ch = blockIdx.y; ch < nch; ch += gridDim.y){
        int j0 = ch << 5;
        __syncthreads();
        for (int e = tid; e < 32*H1; e += 256){
            int jj = e / H1, k = e - jj*H1;
            int j = j0 + jj;
            Bs[(k<<5) + jj] = (j < n) ? g_Brow[j*H1 + k] : 0.0f;
        }
        for (int t = tid; t < 96; t += 256){
            int c = t / 32, jj = t - c*32;
            int j = j0 + jj;
            cj[t] = (j < n) ? ccur[j*3 + c] : 0.0f;
        }
        __syncthreads();
        if (!iv0) continue;   // staging/syncs above run unconditionally

        int j = j0 + lane;
        bool jv = (j < n);
        float jx = cj[lane], jy = cj[32+lane], jz = cj[64+lane];
        float r0x = c0x-jx, r0y = c0y-jy, r0z = c0z-jz;
        float r1x = c1x-jx, r1y = c1y-jy, r1z = c1z-jz;
        float d0 = r0x*r0x + r0y*r0y + r0z*r0z;
        float d1 = r1x*r1x + r1y*r1y + r1z*r1z;
        uint32_t gb0 = grow0[ch];
        uint32_t gb1 = iv1 ? grow1[ch] : 0u;
        float ge0 = ((gb0 >> lane) & 1u) ? 1.0f : 0.0f;
        float ge1 = ((gb1 >> lane) & 1u) ? 1.0f : 0.0f;

        // packed accumulators: 9 pairs per row (t=0..16, t=17 is zero pad)
        ull m2a[9], m2b[9];
        #pragma unroll
        for (int tp = 0; tp < 9; tp++){ m2a[tp] = be2u[tp]; m2b[tp] = m2a[tp]; }

        #pragma unroll 2
        for (int k = 0; k < H1; k++){
            float2 ap = *(const float2*)(As2 + (k<<4) + 2*wi);
            float2 wv = *(const float2*)(wde + 2*k);
            float bsv = Bs[(k<<5) + lane];
            float p0 = ap.x + bsv; p0 = fmaf(d0, wv.x, p0); p0 = fmaf(ge0, wv.y, p0);
            float p1 = ap.y + bsv; p1 = fmaf(d1, wv.x, p1); p1 = fmaf(ge1, wv.y, p1);
            float s0 = siluf(p0), s1 = siluf(p1);
            ull s0d = dup2(s0), s1d = dup2(s1);
            const ull* q = (const ull*)(ws + k*20);
            #pragma unroll
            for (int tp = 0; tp < 9; tp++){
                ull qv = q[tp];
                m2a[tp] = fma2(s0d, qv, m2a[tp]);
                m2b[tp] = fma2(s1d, qv, m2b[tp]);
            }
        }

        // unpack + silu (all constant indices -> registers)
        float me0[MD], me1[MD];
        #pragma unroll
        for (int tp = 0; tp < 9; tp++){
            float x0, x1, y0, y1;
            unpk(m2a[tp], x0, x1); unpk(m2b[tp], y0, y1);
            me0[2*tp] = siluf(x0); me1[2*tp] = siluf(y0);
            if (2*tp + 1 < MD){ me0[2*tp+1] = siluf(x1); me1[2*tp+1] = siluf(y1); }
        }

        float cw0 = coor_mlp(me0, wc14, bc14, wc24, bc2v);
        float cw1 = iv1 ? coor_mlp(me1, wc14, bc14, wc24, bc2v) : 0.0f;

        float mask = jv ? 1.0f : 0.0f;
        reduce_row(ia, me0, cw0, r0x, r0y, r0z, mask, lane, cnext);
        if (iv1) reduce_row(ib, me1, cw1, r1x, r1y, r1z, mask, lane, cnext);
    }
}

// fused node MLP + next-layer A/B prep:
// hc = relu(2*hc + MLP([hc, m_i])); if do_ab: A/B for next layer + zero mi + coor init
__global__ void k_nodeAB(int n, const float* __restrict__ Wn1L, const float* __restrict__ bn1L,
                         const float* __restrict__ Wn2L, const float* __restrict__ bn2L,
                         const float* __restrict__ We1N, const float* __restrict__ be1N,
                         int do_ab, int flag_next){
    __shared__ float in[81];
    __shared__ float z[128];
    __shared__ float hnew[DIMF];
    int i = blockIdx.x, tid = threadIdx.x;
    if (tid < DIMF) in[tid] = g_hc[i*DIMF + tid];
    else if (tid < 81) in[tid] = g_mi[i*MD + (tid - DIMF)];
    __syncthreads();
    if (tid < 128){
        float acc = bn1L[tid];
        #pragma unroll 1
        for (int k = 0; k < 81; k++) acc = fmaf(in[k], Wn1L[k*128 + tid], acc);
        z[tid] = siluf(acc);
    }
    __syncthreads();
    if (tid < DIMF){
        float a2 = bn2L[tid];
        #pragma unroll 1
        for (int k = 0; k < 128; k++) a2 = fmaf(z[k], Wn2L[k*DIMF + tid], a2);
        float v = fmaxf(2.0f*in[tid] + a2, 0.0f);
        hnew[tid] = v;
        g_hc[i*DIMF + tid] = v;
    }
    if (!do_ab) return;
    if (tid >= DIMF && tid < DIMF + MD) g_mi[i*MD + (tid - DIMF)] = 0.0f;
    else if (tid >= DIMF + MD && tid < DIMF + MD + 3){
        int c = tid - DIMF - MD;
        float* cn = flag_next ? g_cA : g_cB;
        const float* cc = flag_next ? g_cB : g_cA;
        cn[i*3 + c] = cc[i*3 + c];
    }
    __syncthreads();
    for (int k = tid; k < H1; k += 256){
        float a = be1N[k], b = 0.0f;
        #pragma unroll
        for (int d = 0; d < DIMF; d++){
            a = fmaf(hnew[d], We1N[d*H1 + k], a);
            b = fmaf(hnew[d], We1N[(DIMF + d)*H1 + k], b);
        }
        g_Arow[i*H1 + k] = a;
        g_Brow[i*H1 + k] = b;
    }
}

__global__ void k_scatter(float* out){
    int i = blockIdx.x, t = threadIdx.x;
    int a = g_idx[i];
    float v = g_hc[i*DIMF + t];
    float* o = &out[a*DIMF + t];
    *o = fmaxf(*o, v);
}

// ---------------- host ----------------
extern "C" void kernel_launch(void* const* d_in, const int* in_sizes, int n_in,
                              void* d_out, int out_size){
    const float* feat = (const float*)d_in[0];
    const float* coor = (const float*)d_in[1];
    const float* edge = (const float*)d_in[2];
    const float* We1  = (const float*)d_in[3];
    const float* be1  = (const float*)d_in[4];
    const float* We2  = (const float*)d_in[5];
    const float* be2  = (const float*)d_in[6];
    const float* Wc1  = (const float*)d_in[7];
    const float* bc1  = (const float*)d_in[8];
    const float* Wc2  = (const float*)d_in[9];
    const float* bc2  = (const float*)d_in[10];
    const float* Wn1  = (const float*)d_in[11];
    const float* bn1  = (const float*)d_in[12];
    const float* Wn2  = (const float*)d_in[13];
    const float* bn2  = (const float*)d_in[14];
    const float* wp   = (const float*)d_in[15];
    const float* bp   = (const float*)d_in[16];
    float* out = (float*)d_out;

    static const int KC[3] = {460, 358, 307};
    const int EDGE_SMEM = 19612 * 4;          // 78448 B
    cudaFuncSetAttribute(k_edge, cudaFuncAttributeMaxDynamicSharedMemorySize, EDGE_SMEM);

    k_zero_out<<<128, 256>>>(out);
    k_ugbits<<<512, 512>>>(edge);
    k_ug2<<<512, 32>>>();

    for (int p = 0; p < 3; p++){
        int n = KC[p];
        int nch = (n + 31) >> 5;
        int gx  = (n + RPB - 1) / RPB;
        int nspl = 296 / gx; if (nspl < 1) nspl = 1; if (nspl > nch) nspl = nch;

        k_select2<<<1, 512>>>(n, feat, coor, wp, bp, p);
        k_gsub<<<n, 32>>>(n);
        k_AB<<<n, 256>>>(n, We1, be1, 0);   // layer 0 prep (cnext=cB from cA, mi=0)
        for (int l = 0; l < 3; l++){
            dim3 ge(gx, nspl);
            k_edge<<<ge, 256, EDGE_SMEM>>>(n, l & 1,
                We1 + l*130*H1, We2 + l*H1*MD, be2 + l*MD,
                Wc1 + l*MD*CHID, bc1 + l*CHID, Wc2 + l*CHID, bc2 + l);
            int ln = (l < 2) ? (l + 1) : 2;
            k_nodeAB<<<n, 256>>>(n,
                Wn1 + l*81*128, bn1 + l*128, Wn2 + l*128*DIMF, bn2 + l*DIMF,
                We1 + ln*130*H1, be1 + ln*H1,
                (l < 2) ? 1 : 0, (l + 1) & 1);
        }
        k_scatter<<<n, 64>>>(out);
    }
}

// round 6
// speedup vs baseline: 1.2094x; 1.0538x over previous
#include <cuda_runtime.h>
#include <stdint.h>

#define NFULL 512
#define DIMF  64
#define H1    260   // 2*EIN
#define MD    17
#define CHID  68
#define NMAX  460
#define RPB   16    // rows per block (8 warps x 2 rows)

typedef unsigned long long ull;

// ---------------- device scratch ----------------
__device__ uint32_t g_ugbits[NFULL*16];
__device__ uint32_t g_ug2bits[NFULL*16];
__device__ float    g_scores[NFULL];
__device__ int      g_idx[NFULL];
__device__ uint32_t g_gsub[NMAX*16];
__device__ float    g_hc[NMAX*DIMF];
__device__ float    g_cA[NMAX*3];
__device__ float    g_cB[NMAX*3];
__device__ float    g_Arow[NMAX*H1];
__device__ float    g_Brow[NMAX*H1];
__device__ float    g_mi[NMAX*MD];

// ---------------- helpers ----------------
__device__ __forceinline__ float ex2a(float x){ float y; asm("ex2.approx.ftz.f32 %0, %1;" : "=f"(y) : "f"(x)); return y; }
__device__ __forceinline__ float rcpa(float x){ float y; asm("rcp.approx.ftz.f32 %0, %1;" : "=f"(y) : "f"(x)); return y; }
__device__ __forceinline__ float siluf(float x){
    return x * rcpa(1.0f + ex2a(-1.4426950408889634f * x));
}
__device__ __forceinline__ ull pk2(float lo, float hi){
    ull r; asm("mov.b64 %0, {%1,%2};" : "=l"(r) : "r"(__float_as_uint(lo)), "r"(__float_as_uint(hi))); return r;
}
__device__ __forceinline__ ull dup2(float v){
    ull r; asm("mov.b64 %0, {%1,%1};" : "=l"(r) : "r"(__float_as_uint(v))); return r;
}
__device__ __forceinline__ void unpk(ull v, float& lo, float& hi){
    unsigned a, b;
    asm("mov.b64 {%0,%1}, %2;" : "=r"(a), "=r"(b) : "l"(v));
    lo = __uint_as_float(a); hi = __uint_as_float(b);
}
__device__ __forceinline__ ull fma2(ull a, ull b, ull c){
    ull d; asm("fma.rn.f32x2 %0, %1, %2, %3;" : "=l"(d) : "l"(a), "l"(b), "l"(c)); return d;
}
__device__ __forceinline__ ull add2(ull a, ull b){
    ull d; asm("add.rn.f32x2 %0, %1, %2;" : "=l"(d) : "l"(a), "l"(b)); return d;
}
__device__ __forceinline__ ull mul2(ull a, ull b){
    ull d; asm("mul.rn.f32x2 %0, %1, %2;" : "=l"(d) : "l"(a), "l"(b)); return d;
}
// packed silu over the 2 lanes of an f32x2
__device__ __forceinline__ ull silu2(ull x){
    ull t = mul2(x, dup2(-1.4426950408889634f));
    float t0, t1; unpk(t, t0, t1);
    ull e = add2(pk2(ex2a(t0), ex2a(t1)), dup2(1.0f));
    float u0, u1; unpk(e, u0, u1);
    return mul2(x, pk2(rcpa(u0), rcpa(u1)));
}

// ---------------- misc kernels ----------------
__global__ void k_zero_out(float* out){
    int t = blockIdx.x*blockDim.x + threadIdx.x;
    if (t < NFULL*DIMF) out[t] = 0.0f;
}

__global__ void k_ugbits(const float* __restrict__ edge){
    int a = blockIdx.x, c = threadIdx.x;
    bool b = edge[a*NFULL + c] != 0.0f;
    unsigned m = __ballot_sync(0xffffffffu, b);
    if ((c & 31) == 0) g_ugbits[a*16 + (c>>5)] = m;
}

__global__ void k_ug2(){
    __shared__ uint32_t row[16];
    int a = blockIdx.x, lane = threadIdx.x;
    if (lane < 16) row[lane] = g_ugbits[a*16 + lane];
    __syncwarp();
    uint32_t acc = 0;
    for (int c = 0; c < NFULL; c++){
        if ((row[c>>5] >> (c&31)) & 1u){
            if (lane < 16) acc |= g_ugbits[c*16 + lane];
        }
    }
    if (lane < 16) g_ug2bits[a*16 + lane] = acc;
}

__global__ void k_scores(const float* __restrict__ feat, const float* __restrict__ wp,
                         const float* __restrict__ bp, int pool){
    int tid = threadIdx.x, lane = tid & 31;
    int a = blockIdx.x*4 + (tid >> 5);
    const float* w = wp + pool*DIMF;
    float v = feat[a*DIMF + lane]*w[lane] + feat[a*DIMF + 32 + lane]*w[32 + lane];
    for (int off = 16; off; off >>= 1) v += __shfl_xor_sync(0xffffffffu, v, off);
    if (lane == 0){
        v += bp[pool];
        g_scores[a] = rcpa(1.0f + ex2a(-1.4426950408889634f * v));
    }
}

// parallel rank: selected node's compacted slot IS its rank (set semantics OK:
// EGNN is permutation-equivariant and the final scatter restores positions)
__global__ void k_rank(int kcnt){
    __shared__ int ired[4];
    int a = blockIdx.x;
    float s = g_scores[a];
    int tid = threadIdx.x, lane = tid & 31, w = tid >> 5;
    int r = 0;
    for (int b = tid; b < NFULL; b += 128){
        float sb = g_scores[b];
        r += (sb > s) || (sb == s && b < a);
    }
    for (int off = 16; off; off >>= 1) r += __shfl_xor_sync(0xffffffffu, r, off);
    if (lane == 0) ired[w] = r;
    __syncthreads();
    if (tid == 0){
        int rt = ired[0] + ired[1] + ired[2] + ired[3];
        if (rt < kcnt) g_idx[rt] = a;
    }
}

__global__ void k_gather(const float* __restrict__ feat, const float* __restrict__ coor){
    int i = blockIdx.x, t = threadIdx.x;
    int a = g_idx[i];
    float s = g_scores[a];
    g_hc[i*DIMF + t] = feat[a*DIMF + t] * s;
    if (t < 3) g_cA[i*3 + t] = coor[a*3 + t];
}

__global__ void k_gsub(int n){
    int i = blockIdx.x, lane = threadIdx.x;
    int gi = g_idx[i];
    for (int w = 0; w < 16; w++){
        int j = w*32 + lane;
        bool bit = false;
        if (j < n){
            int gj = g_idx[j];
            bit = (g_ug2bits[gi*16 + (gj>>5)] >> (gj&31)) & 1u;
        }
        unsigned m = __ballot_sync(0xffffffffu, bit);
        if (lane == 0) g_gsub[i*16 + w] = m;
    }
}

// A = h@We1[0:64] + be1, B = h@We1[64:128]; also zero m_i and init coor_next
__global__ void k_AB(int n, const float* __restrict__ We1L, const float* __restrict__ be1L, int flag){
    __shared__ float h[DIMF];
    int i = blockIdx.x, tid = threadIdx.x;
    if (tid < DIMF) h[tid] = g_hc[i*DIMF + tid];
    else if (tid < DIMF + MD) g_mi[i*MD + (tid - DIMF)] = 0.0f;
    else if (tid < DIMF + MD + 3){
        int c = tid - DIMF - MD;
        float* cnext = flag ? g_cA : g_cB;
        const float* ccur = flag ? g_cB : g_cA;
        cnext[i*3 + c] = ccur[i*3 + c];
    }
    __syncthreads();
    for (int k = tid; k < H1; k += 256){
        float a = be1L[k], b = 0.0f;
        #pragma unroll
        for (int d = 0; d < DIMF; d++){
            a = fmaf(h[d], We1L[d*H1 + k], a);
            b = fmaf(h[d], We1L[(DIMF + d)*H1 + k], b);
        }
        g_Arow[i*H1 + k] = a;
        g_Brow[i*H1 + k] = b;
    }
}

// ---------------- reduction helper (constant indexing) ----------------
__device__ __forceinline__ void reduce_row(int row, const float (&me)[MD], float cwv,
        float rx, float ry, float rz, float mask, int lane, float* __restrict__ cnext){
    #pragma unroll
    for (int t = 0; t < MD; t++){
        float v = me[t] * mask;
        for (int off = 16; off; off >>= 1) v += __shfl_xor_sync(0xffffffffu, v, off);
        if (lane == 0) atomicAdd(&g_mi[row*MD + t], v);
    }
    float vx = cwv*rx*mask, vy = cwv*ry*mask, vz = cwv*rz*mask;
    for (int off = 16; off; off >>= 1){
        vx += __shfl_xor_sync(0xffffffffu, vx, off);
        vy += __shfl_xor_sync(0xffffffffu, vy, off);
        vz += __shfl_xor_sync(0xffffffffu, vz, off);
    }
    if (lane == 0){
        atomicAdd(&cnext[row*3 + 0], vx);
        atomicAdd(&cnext[row*3 + 1], vy);
        atomicAdd(&cnext[row*3 + 2], vz);
    }
}

// ---------------- the heavy edge kernel ----------------
// 256 threads = 8 warps; warp wi handles rows (i0+2wi, i0+2wi+1) sharing lane j.
// Row-pair f32x2 packing everywhere; weights pre-duplicated in smem so packing is free.
__global__ void __launch_bounds__(256, 2) k_edge(int n, int flag,
    const float* __restrict__ We1L, const float* __restrict__ We2L,
    const float* __restrict__ be2L, const float* __restrict__ Wc1L,
    const float* __restrict__ bc1L, const float* __restrict__ Wc2L,
    const float* __restrict__ bc2L)
{
    extern __shared__ float sm[];
    float* wsd  = sm;               // 260*36: We2 rows duplicated (17 pairs + pad)
    float* Bs   = wsd + 9360;       // 260*32: B tile, k-major
    float* As2  = Bs + 8320;        // 260*16: A tile, k-major (row pairs adjacent)
    float* wded = As2 + 4160;       // 260*4: (wd,wd,we,we) per k -> one LDS.128
    float* wc1d = wded + 1040;      // 17*136: Wc1 duplicated
    float* bc1d = wc1d + 2312;      // 136
    float* wc2d = bc1d + 136;       // 136
    float* be2d = wc2d + 136;       // 40 (17 pairs + pad)
    float* cj   = be2d + 40;        // 96
    float* bc2s = cj + 96;          // 4  -> total 25604 floats = 102416 B

    int tid = threadIdx.x, lane = tid & 31, wi = tid >> 5;
    const float* ccur = flag ? g_cB : g_cA;
    float* cnext = flag ? g_cA : g_cB;

    for (int t = tid; t < 9360; t += 256){
        int k = t / 36, c = t - 36*k;
        wsd[t] = (c < 34) ? We2L[k*MD + (c >> 1)] : 0.0f;
    }
    for (int t = tid; t < H1; t += 256){
        float wd = We1L[128*H1 + t], we = We1L[129*H1 + t];
        wded[4*t+0] = wd; wded[4*t+1] = wd; wded[4*t+2] = we; wded[4*t+3] = we;
    }
    for (int e = tid; e < MD*CHID; e += 256){
        int t = e / CHID, h = e - t*CHID;
        float v = Wc1L[e];
        wc1d[t*136 + 2*h] = v; wc1d[t*136 + 2*h + 1] = v;
    }
    if (tid < CHID){
        float v1 = bc1L[tid]; bc1d[2*tid] = v1; bc1d[2*tid+1] = v1;
        float v2 = Wc2L[tid]; wc2d[2*tid] = v2; wc2d[2*tid+1] = v2;
    }
    if (tid < 20){
        float v = (tid < MD) ? be2L[tid] : 0.0f;
        be2d[2*tid] = v; be2d[2*tid+1] = v;
    }
    if (tid == 0) bc2s[0] = bc2L[0];

    int i0 = blockIdx.x * RPB;
    for (int e = tid; e < RPB*H1; e += 256){
        int r = e / H1, k = e - r*H1;
        int ii = i0 + r;
        As2[(k<<4) + r] = (ii < n) ? g_Arow[ii*H1 + k] : 0.0f;
    }
    __syncthreads();
    const float bc2v = bc2s[0];

    int ia = i0 + 2*wi, ib = ia + 1;
    bool iv0 = (ia < n), iv1 = (ib < n);
    float c0x=0,c0y=0,c0z=0,c1x=0,c1y=0,c1z=0;
    if (iv0){ c0x=ccur[ia*3]; c0y=ccur[ia*3+1]; c0z=ccur[ia*3+2]; }
    if (iv1){ c1x=ccur[ib*3]; c1y=ccur[ib*3+1]; c1z=ccur[ib*3+2]; }
    const uint32_t* grow0 = g_gsub + ia*16;
    const uint32_t* grow1 = g_gsub + ib*16;

    const ull* be2u = (const ull*)be2d;
    const ull* bc1u = (const ull*)bc1d;
    const ull* wc2u = (const ull*)wc2d;

    int nch = (n + 31) >> 5;
    for (int ch = blockIdx.y; ch < nch; ch += gridDim.y){
        int j0 = ch << 5;
        __syncthreads();
        for (int e = tid; e < 32*H1; e += 256){
            int jj = e / H1, k = e - jj*H1;
            int j = j0 + jj;
            Bs[(k<<5) + jj] = (j < n) ? g_Brow[j*H1 + k] : 0.0f;
        }
        for (int t = tid; t < 96; t += 256){
            int c = t / 32, jj = t - c*32;
            int j = j0 + jj;
            cj[t] = (j < n) ? ccur[j*3 + c] : 0.0f;
        }
        __syncthreads();
        if (!iv0) continue;   // staging/syncs above run unconditionally

        int j = j0 + lane;
        bool jv = (j < n);
        float jx = cj[lane], jy = cj[32+lane], jz = cj[64+lane];
        float r0x = c0x-jx, r0y = c0y-jy, r0z = c0z-jz;
        float r1x = c1x-jx, r1y = c1y-jy, r1z = c1z-jz;
        float d0 = r0x*r0x + r0y*r0y + r0z*r0z;
        float d1 = r1x*r1x + r1y*r1y + r1z*r1z;
        uint32_t gb0 = grow0[ch];
        uint32_t gb1 = iv1 ? grow1[ch] : 0u;
        ull d01  = pk2(d0, d1);
        ull ge01 = pk2(((gb0 >> lane) & 1u) ? 1.0f : 0.0f,
                       ((gb1 >> lane) & 1u) ? 1.0f : 0.0f);

        // 17 packed accumulators: lane0 = row a, lane1 = row b
        ull m01[MD];
        #pragma unroll
        for (int t = 0; t < MD; t++) m01[t] = be2u[t];

        #pragma unroll 2
        for (int k = 0; k < H1; k++){
            ull ap = *(const ull*)(As2 + (k<<4) + 2*wi);   // (A_ia, A_ib)
            float4 wq = *(const float4*)(wded + (k<<2));   // (wd,wd,we,we)
            float bsv = Bs[(k<<5) + lane];
            ull pre = add2(ap, dup2(bsv));
            pre = fma2(d01, pk2(wq.x, wq.y), pre);
            pre = fma2(ge01, pk2(wq.z, wq.w), pre);
            ull s01 = silu2(pre);
            const ull* q = (const ull*)(wsd + k*36);       // duplicated We2 row
            #pragma unroll
            for (int t = 0; t < MD; t++) m01[t] = fma2(s01, q[t], m01[t]);
        }

        // me = silu(m) in place, still packed by rows
        #pragma unroll
        for (int t = 0; t < MD; t++) m01[t] = silu2(m01[t]);

        // coor MLP, packed by rows, 2 hidden units per iteration
        ull cw01 = dup2(bc2v);
        #pragma unroll 2
        for (int h2 = 0; h2 < CHID/2; h2++){
            ull a0 = bc1u[2*h2], a1 = bc1u[2*h2 + 1];
            #pragma unroll
            for (int t = 0; t < MD; t++){
                float4 wv = ((const float4*)(wc1d + t*136))[h2];  // (w_h,w_h,w_h1,w_h1)
                a0 = fma2(m01[t], pk2(wv.x, wv.y), a0);
                a1 = fma2(m01[t], pk2(wv.z, wv.w), a1);
            }
            a0 = silu2(a0); a1 = silu2(a1);
            cw01 = fma2(a0, wc2u[2*h2], cw01);
            cw01 = fma2(a1, wc2u[2*h2 + 1], cw01);
        }
        float cw0, cw1; unpk(cw01, cw0, cw1);

        float me0[MD], me1[MD];
        #pragma unroll
        for (int t = 0; t < MD; t++) unpk(m01[t], me0[t], me1[t]);

        float mask = jv ? 1.0f : 0.0f;
        reduce_row(ia, me0, cw0, r0x, r0y, r0z, mask, lane, cnext);
        if (iv1) reduce_row(ib, me1, cw1, r1x, r1y, r1z, mask, lane, cnext);
    }
}

// fused node MLP + next-layer A/B prep
__global__ void k_nodeAB(int n, const float* __restrict__ Wn1L, const float* __restrict__ bn1L,
                         const float* __restrict__ Wn2L, const float* __restrict__ bn2L,
                         const float* __restrict__ We1N, const float* __restrict__ be1N,
                         int do_ab, int flag_next){
    __shared__ float in[81];
    __shared__ float z[128];
    __shared__ float hnew[DIMF];
    int i = blockIdx.x, tid = threadIdx.x;
    if (tid < DIMF) in[tid] = g_hc[i*DIMF + tid];
    else if (tid < 81) in[tid] = g_mi[i*MD + (tid - DIMF)];
    __syncthreads();
    if (tid < 128){
        float acc = bn1L[tid];
        #pragma unroll 1
        for (int k = 0; k < 81; k++) acc = fmaf(in[k], Wn1L[k*128 + tid], acc);
        z[tid] = siluf(acc);
    }
    __syncthreads();
    if (tid < DIMF){
        float a2 = bn2L[tid];
        #pragma unroll 1
        for (int k = 0; k < 128; k++) a2 = fmaf(z[k], Wn2L[k*DIMF + tid], a2);
        float v = fmaxf(2.0f*in[tid] + a2, 0.0f);
        hnew[tid] = v;
        g_hc[i*DIMF + tid] = v;
    }
    if (!do_ab) return;
    if (tid >= DIMF && tid < DIMF + MD) g_mi[i*MD + (tid - DIMF)] = 0.0f;
    else if (tid >= DIMF + MD && tid < DIMF + MD + 3){
        int c = tid - DIMF - MD;
        float* cn = flag_next ? g_cA : g_cB;
        const float* cc = flag_next ? g_cB : g_cA;
        cn[i*3 + c] = cc[i*3 + c];
    }
    __syncthreads();
    for (int k = tid; k < H1; k += 256){
        float a = be1N[k], b = 0.0f;
        #pragma unroll
        for (int d = 0; d < DIMF; d++){
            a = fmaf(hnew[d], We1N[d*H1 + k], a);
            b = fmaf(hnew[d], We1N[(DIMF + d)*H1 + k], b);
        }
        g_Arow[i*H1 + k] = a;
        g_Brow[i*H1 + k] = b;
    }
}

__global__ void k_scatter(float* out){
    int i = blockIdx.x, t = threadIdx.x;
    int a = g_idx[i];
    float v = g_hc[i*DIMF + t];
    float* o = &out[a*DIMF + t];
    *o = fmaxf(*o, v);
}

// ---------------- host ----------------
extern "C" void kernel_launch(void* const* d_in, const int* in_sizes, int n_in,
                              void* d_out, int out_size){
    const float* feat = (const float*)d_in[0];
    const float* coor = (const float*)d_in[1];
    const float* edge = (const float*)d_in[2];
    const float* We1  = (const float*)d_in[3];
    const float* be1  = (const float*)d_in[4];
    const float* We2  = (const float*)d_in[5];
    const float* be2  = (const float*)d_in[6];
    const float* Wc1  = (const float*)d_in[7];
    const float* bc1  = (const float*)d_in[8];
    const float* Wc2  = (const float*)d_in[9];
    const float* bc2  = (const float*)d_in[10];
    const float* Wn1  = (const float*)d_in[11];
    const float* bn1  = (const float*)d_in[12];
    const float* Wn2  = (const float*)d_in[13];
    const float* bn2  = (const float*)d_in[14];
    const float* wp   = (const float*)d_in[15];
    const float* bp   = (const float*)d_in[16];
    float* out = (float*)d_out;

    static const int KC[3] = {460, 358, 307};
    const int EDGE_SMEM = 25604 * 4;          // 102416 B
    cudaFuncSetAttribute(k_edge, cudaFuncAttributeMaxDynamicSharedMemorySize, EDGE_SMEM);

    k_zero_out<<<128, 256>>>(out);
    k_ugbits<<<512, 512>>>(edge);
    k_ug2<<<512, 32>>>();

    for (int p = 0; p < 3; p++){
        int n = KC[p];
        int nch = (n + 31) >> 5;
        int gx  = (n + RPB - 1) / RPB;
        int nspl = 296 / gx; if (nspl < 1) nspl = 1; if (nspl > nch) nspl = nch;

        k_scores<<<128, 128>>>(feat, wp, bp, p);
        k_rank<<<NFULL, 128>>>(n);
        k_gather<<<n, 64>>>(feat, coor);
        k_gsub<<<n, 32>>>(n);
        k_AB<<<n, 256>>>(n, We1, be1, 0);   // layer 0 prep
        for (int l = 0; l < 3; l++){
            dim3 ge(gx, nspl);
            k_edge<<<ge, 256, EDGE_SMEM>>>(n, l & 1,
                We1 + l*130*H1, We2 + l*H1*MD, be2 + l*MD,
                Wc1 + l*MD*CHID, bc1 + l*CHID, Wc2 + l*CHID, bc2 + l);
            int ln = (l < 2) ? (l + 1) : 2;
            k_nodeAB<<<n, 256>>>(n,
                Wn1 + l*81*128, bn1 + l*128, Wn2 + l*128*DIMF, bn2 + l*DIMF,
                We1 + ln*130*H1, be1 + ln*H1,
                (l < 2) ? 1 : 0, (l + 1) & 1);
        }
        k_scatter<<<n, 64>>>(out);
    }
}

// round 7
// speedup vs baseline: 1.7180x; 1.4205x over previous
#include <cuda_runtime.h>
#include <stdint.h>

#define NFULL 512
#define DIMF  64
#define H1    260
#define MD    17
#define CHID  68
#define NMAX  460
#define N0 460
#define N1 358
#define N2 307
#define NTOT 1125
// edge grid: gx {15,12,10}, nspl {9,7,6} -> blocks {135,84,60} = 279 (one wave @2/SM)
#define EGRID 279

typedef unsigned long long ull;

// ---------------- device scratch (per-pool batched) ----------------
__device__ uint32_t g_ugbits[NFULL*16];
__device__ uint32_t g_ug2bits[NFULL*16];
__device__ float    g_scores[3*NFULL];
__device__ int      g_idx[3*NFULL];
__device__ uint32_t g_gsub[3*NMAX*16];
__device__ float    g_hc[3*NMAX*DIMF];
__device__ float    g_cA[3*NMAX*3];
__device__ float    g_cB[3*NMAX*3];
__device__ float    g_Arow[3*NMAX*H1];
__device__ float    g_Brow[3*NMAX*H1];
__device__ float    g_mi[3*NMAX*MD];

// ---------------- helpers ----------------
__device__ __forceinline__ float ex2a(float x){ float y; asm("ex2.approx.ftz.f32 %0, %1;" : "=f"(y) : "f"(x)); return y; }
__device__ __forceinline__ float rcpa(float x){ float y; asm("rcp.approx.ftz.f32 %0, %1;" : "=f"(y) : "f"(x)); return y; }
__device__ __forceinline__ float tanha(float x){ float y; asm("tanh.approx.f32 %0, %1;" : "=f"(y) : "f"(x)); return y; }
__device__ __forceinline__ float siluf(float x){
    return x * rcpa(1.0f + ex2a(-1.4426950408889634f * x));
}
__device__ __forceinline__ float sigf(float x){
    return rcpa(1.0f + ex2a(-1.4426950408889634f * x));
}
__device__ __forceinline__ ull pk2(float lo, float hi){
    ull r; asm("mov.b64 %0, {%1,%2};" : "=l"(r) : "r"(__float_as_uint(lo)), "r"(__float_as_uint(hi))); return r;
}
__device__ __forceinline__ ull dup2(float v){
    ull r; asm("mov.b64 %0, {%1,%1};" : "=l"(r) : "r"(__float_as_uint(v))); return r;
}
__device__ __forceinline__ void unpk(ull v, float& lo, float& hi){
    unsigned a, b;
    asm("mov.b64 {%0,%1}, %2;" : "=r"(a), "=r"(b) : "l"(v));
    lo = __uint_as_float(a); hi = __uint_as_float(b);
}
__device__ __forceinline__ ull fma2(ull a, ull b, ull c){
    ull d; asm("fma.rn.f32x2 %0, %1, %2, %3;" : "=l"(d) : "l"(a), "l"(b), "l"(c)); return d;
}
__device__ __forceinline__ ull add2(ull a, ull b){
    ull d; asm("add.rn.f32x2 %0, %1, %2;" : "=l"(d) : "l"(a), "l"(b)); return d;
}
__device__ __forceinline__ ull mul2(ull a, ull b){
    ull d; asm("mul.rn.f32x2 %0, %1, %2;" : "=l"(d) : "l"(a), "l"(b)); return d;
}
// fast inner-loop packed silu via tanh: silu(x) = h + h*tanh(h), h = x/2
__device__ __forceinline__ ull silu2t(ull x, ull HALF2){
    ull h = mul2(x, HALF2);
    float h0, h1; unpk(h, h0, h1);
    ull t = pk2(tanha(h0), tanha(h1));
    return fma2(h, t, h);
}
// exact packed silu (epilogue)
__device__ __forceinline__ ull silu2x(ull x){
    ull t = mul2(x, dup2(-1.4426950408889634f));
    float t0, t1; unpk(t, t0, t1);
    ull e = add2(pk2(ex2a(t0), ex2a(t1)), dup2(1.0f));
    float u0, u1; unpk(e, u0, u1);
    return mul2(x, pk2(rcpa(u0), rcpa(u1)));
}
__device__ __forceinline__ ull shflx2(ull v, int off){
    float lo, hi; unpk(v, lo, hi);
    lo = __shfl_xor_sync(0xffffffffu, lo, off);
    hi = __shfl_xor_sync(0xffffffffu, hi, off);
    return pk2(lo, hi);
}
__device__ __forceinline__ void pool_of(int bid, int& p, int& i, int& n){
    if (bid < N0){ p = 0; i = bid; n = N0; }
    else if (bid < N0+N1){ p = 1; i = bid - N0; n = N1; }
    else { p = 2; i = bid - N0 - N1; n = N2; }
}

// ---------------- launch 0: zero output ----------------
__global__ void k_zero_out(float* out){
    int t = blockIdx.x*blockDim.x + threadIdx.x;
    if (t < NFULL*DIMF) out[t] = 0.0f;
}

// ---------------- launch 1: adjacency bits + pool scores ----------------
__global__ void k_ugbits_scores(const float* __restrict__ edge, const float* __restrict__ feat,
                                const float* __restrict__ wp, const float* __restrict__ bp){
    int a = blockIdx.x, tid = threadIdx.x, lane = tid & 31, w = tid >> 5;
    bool b = edge[a*NFULL + tid] != 0.0f;
    unsigned m = __ballot_sync(0xffffffffu, b);
    if (lane == 0) g_ugbits[a*16 + w] = m;
    if (w < 3){
        float v = feat[a*DIMF + lane]*wp[w*DIMF + lane]
                + feat[a*DIMF + 32 + lane]*wp[w*DIMF + 32 + lane];
        for (int off = 16; off; off >>= 1) v += __shfl_xor_sync(0xffffffffu, v, off);
        if (lane == 0) g_scores[w*NFULL + a] = sigf(v + bp[w]);
    }
}

// ---------------- launch 2: ug2 = (ug@ug != 0) ----------------
__global__ void k_ug2(){
    __shared__ uint32_t row[16];
    int a = blockIdx.x, lane = threadIdx.x;
    if (lane < 16) row[lane] = g_ugbits[a*16 + lane];
    __syncwarp();
    uint32_t acc = 0;
    for (int c = 0; c < NFULL; c++){
        if ((row[c>>5] >> (c&31)) & 1u){
            if (lane < 16) acc |= g_ugbits[c*16 + lane];
        }
    }
    if (lane < 16) g_ug2bits[a*16 + lane] = acc;
}

// ---------------- launch 3: rank -> compacted slot (all 3 pools) ----------------
__global__ void k_rank(){
    __shared__ int ired[4];
    int p = blockIdx.y, a = blockIdx.x;
    int kcnt = (p == 0) ? N0 : (p == 1) ? N1 : N2;
    const float* sc = g_scores + p*NFULL;
    float s = sc[a];
    int tid = threadIdx.x, lane = tid & 31, w = tid >> 5;
    int r = 0;
    for (int b = tid; b < NFULL; b += 128){
        float sb = sc[b];
        r += (sb > s) || (sb == s && b < a);
    }
    for (int off = 16; off; off >>= 1) r += __shfl_xor_sync(0xffffffffu, r, off);
    if (lane == 0) ired[w] = r;
    __syncthreads();
    if (tid == 0){
        int rt = ired[0] + ired[1] + ired[2] + ired[3];
        if (rt < kcnt) g_idx[p*NFULL + rt] = a;
    }
}

// ---------------- launch 4: prep = gather + gsub + layer0 A/B + inits ----------------
__global__ void k_prep(const float* __restrict__ feat, const float* __restrict__ coor,
                       const float* __restrict__ We1, const float* __restrict__ be1){
    __shared__ float h[DIMF];
    int p, i, n; pool_of(blockIdx.x, p, i, n);
    const int* idx = g_idx + p*NFULL;
    int a = idx[i];
    int tid = threadIdx.x, lane = tid & 31;
    float s = g_scores[p*NFULL + a];
    if (tid < DIMF){
        float v = feat[a*DIMF + tid] * s;
        h[tid] = v;
        g_hc[p*NMAX*DIMF + i*DIMF + tid] = v;
    } else if (tid < DIMF + 3){
        int c = tid - DIMF;
        float cv = coor[a*3 + c];
        g_cA[p*NMAX*3 + i*3 + c] = cv;
        g_cB[p*NMAX*3 + i*3 + c] = cv;
    } else if (tid < DIMF + 3 + MD){
        g_mi[p*NMAX*MD + i*MD + (tid - DIMF - 3)] = 0.0f;
    } else if (tid >= 128){
        int w = (tid >> 5) - 4;  // 0..3, full warps
        for (int q = 0; q < 4; q++){
            int wd = w*4 + q, j = wd*32 + lane;
            bool bit = false;
            if (j < n){
                int gj = idx[j];
                bit = (g_ug2bits[a*16 + (gj>>5)] >> (gj&31)) & 1u;
            }
            unsigned m = __ballot_sync(0xffffffffu, bit);
            if (lane == 0) g_gsub[p*NMAX*16 + i*16 + wd] = m;
        }
    }
    __syncthreads();
    float* Ar = g_Arow + p*NMAX*H1 + i*H1;
    float* Br = g_Brow + p*NMAX*H1 + i*H1;
    for (int k = tid; k < H1; k += 256){
        float av = be1[k], bv = 0.0f;
        #pragma unroll
        for (int d = 0; d < DIMF; d++){
            av = fmaf(h[d], We1[d*H1 + k], av);
            bv = fmaf(h[d], We1[(DIMF + d)*H1 + k], bv);
        }
        Ar[k] = av;
        Br[k] = bv;
    }
}

// ---------------- the heavy edge kernel (all 3 pools, 4 rows/warp) ----------------
__global__ void __launch_bounds__(256, 2) k_edge(int flag,
    const float* __restrict__ We1L, const float* __restrict__ We2L,
    const float* __restrict__ be2L, const float* __restrict__ Wc1L,
    const float* __restrict__ bc1L, const float* __restrict__ Wc2L,
    const float* __restrict__ bc2L)
{
    extern __shared__ float sm[];
    float* wsd  = sm;               // 260*36: We2 rows duplicated pairs (LDS.128-able)
    float* Bs   = wsd + 9360;       // 260*33: B tile, k-major, conflict-free staging
    float* As2  = Bs + 8580;        // 260*32: A tile, k-major, 32 rows
    float* wdes = As2 + 8320;       // 260*2: (wd,we) interleaved
    float* wc1  = wdes + 520;       // 17*68
    float* bc1d = wc1 + 1156;       // 136 (duplicated)
    float* wc2d = bc1d + 136;       // 136 (duplicated)
    float* be2d = wc2d + 136;       // 34 (duplicated)
    float* cj   = be2d + 34;        // 96
    float* bc2s = cj + 96;          // 2  -> 28340 floats = 113360 B

    // pool decode
    int bid = blockIdx.x, p, lb, gx, nspl, n, nch;
    if (bid < 135){ p = 0; lb = bid;       gx = 15; nspl = 9; n = N0; nch = 15; }
    else if (bid < 219){ p = 1; lb = bid - 135; gx = 12; nspl = 7; n = N1; nch = 12; }
    else { p = 2; lb = bid - 219; gx = 10; nspl = 6; n = N2; nch = 10; }
    int bx = lb % gx, by = lb / gx;

    const float* Arow = g_Arow + p*NMAX*H1;
    const float* Brow = g_Brow + p*NMAX*H1;
    const uint32_t* gsub = g_gsub + p*NMAX*16;
    float* mi = g_mi + p*NMAX*MD;
    const float* ccur = (flag ? g_cB : g_cA) + p*NMAX*3;
    float*       cnext = (flag ? g_cA : g_cB) + p*NMAX*3;

    int tid = threadIdx.x, lane = tid & 31, wi = tid >> 5;
    const ull HALF2 = dup2(0.5f);

    // ---- stage weights ----
    for (int t = tid; t < 9360; t += 256){
        int k = t / 36, c = t - 36*k;
        wsd[t] = (c < 34) ? We2L[k*MD + (c >> 1)] : 0.0f;
    }
    for (int t = tid; t < H1; t += 256){
        wdes[2*t]   = We1L[128*H1 + t];
        wdes[2*t+1] = We1L[129*H1 + t];
    }
    for (int t = tid; t < MD*CHID; t += 256) wc1[t] = Wc1L[t];
    if (tid < CHID){
        float v1 = bc1L[tid]; bc1d[2*tid] = v1; bc1d[2*tid+1] = v1;
        float v2 = Wc2L[tid]; wc2d[2*tid] = v2; wc2d[2*tid+1] = v2;
    }
    if (tid < MD){ float v = be2L[tid]; be2d[2*tid] = v; be2d[2*tid+1] = v; }
    if (tid == 0) bc2s[0] = bc2L[0];

    // ---- stage A tile (32 rows) ----
    int i0 = bx * 32;
    for (int e = tid; e < 32*H1; e += 256){
        int r = e / H1, k = e - r*H1;
        int ii = i0 + r;
        As2[(k<<5) + r] = (ii < n) ? Arow[ii*H1 + k] : 0.0f;
    }
    __syncthreads();
    const float bc2v = bc2s[0];

    int ia = i0 + 4*wi;
    bool iv0 = (ia < n), iv1 = (ia+1 < n), iv2 = (ia+2 < n), iv3 = (ia+3 < n);
    float cx0=0,cy0=0,cz0=0,cx1=0,cy1=0,cz1=0,cx2=0,cy2=0,cz2=0,cx3=0,cy3=0,cz3=0;
    if (iv0){ cx0=ccur[ia*3];     cy0=ccur[ia*3+1];     cz0=ccur[ia*3+2]; }
    if (iv1){ cx1=ccur[(ia+1)*3]; cy1=ccur[(ia+1)*3+1]; cz1=ccur[(ia+1)*3+2]; }
    if (iv2){ cx2=ccur[(ia+2)*3]; cy2=ccur[(ia+2)*3+1]; cz2=ccur[(ia+2)*3+2]; }
    if (iv3){ cx3=ccur[(ia+3)*3]; cy3=ccur[(ia+3)*3+1]; cz3=ccur[(ia+3)*3+2]; }

    const ull* be2u = (const ull*)be2d;
    const ull* bc1u = (const ull*)bc1d;
    const ull* wc2u = (const ull*)wc2d;
    const float4* wc1f4 = (const float4*)wc1;

    for (int ch = by; ch < nch; ch += nspl){
        int j0 = ch << 5;
        __syncthreads();
        for (int e = tid; e < 32*H1; e += 256){
            int jj = e / H1, k = e - jj*H1;
            int j = j0 + jj;
            Bs[k*33 + jj] = (j < n) ? Brow[j*H1 + k] : 0.0f;
        }
        for (int t = tid; t < 96; t += 256){
            int c = t / 32, jj = t - c*32;
            int j = j0 + jj;
            cj[t] = (j < n) ? ccur[j*3 + c] : 0.0f;
        }
        __syncthreads();
        if (!iv0) continue;   // staging/syncs above run unconditionally

        int j = j0 + lane;
        bool jv = (j < n);
        float jx = cj[lane], jy = cj[32+lane], jz = cj[64+lane];
        float rx0=cx0-jx, ry0=cy0-jy, rz0=cz0-jz;
        float rx1=cx1-jx, ry1=cy1-jy, rz1=cz1-jz;
        float rx2=cx2-jx, ry2=cy2-jy, rz2=cz2-jz;
        float rx3=cx3-jx, ry3=cy3-jy, rz3=cz3-jz;
        ull dd_ab = pk2(rx0*rx0+ry0*ry0+rz0*rz0, rx1*rx1+ry1*ry1+rz1*rz1);
        ull dd_cd = pk2(rx2*rx2+ry2*ry2+rz2*rz2, rx3*rx3+ry3*ry3+rz3*rz3);
        uint32_t gb0 = iv0 ? gsub[ia*16 + ch] : 0u;
        uint32_t gb1 = iv1 ? gsub[(ia+1)*16 + ch] : 0u;
        uint32_t gb2 = iv2 ? gsub[(ia+2)*16 + ch] : 0u;
        uint32_t gb3 = iv3 ? gsub[(ia+3)*16 + ch] : 0u;
        ull ge_ab = pk2(((gb0>>lane)&1u)?1.0f:0.0f, ((gb1>>lane)&1u)?1.0f:0.0f);
        ull ge_cd = pk2(((gb2>>lane)&1u)?1.0f:0.0f, ((gb3>>lane)&1u)?1.0f:0.0f);

        ull m_ab[MD], m_cd[MD];
        #pragma unroll
        for (int t = 0; t < MD; t++){ m_ab[t] = be2u[t]; m_cd[t] = m_ab[t]; }

        #pragma unroll 2
        for (int k = 0; k < H1; k++){
            ull ap_ab = *(const ull*)(As2 + (k<<5) + 4*wi);
            ull ap_cd = *(const ull*)(As2 + (k<<5) + 4*wi + 2);
            float2 wv = *(const float2*)(wdes + 2*k);
            ull wdd = dup2(wv.x), wed = dup2(wv.y);
            ull bsvd = dup2(Bs[k*33 + lane]);
            ull pre_ab = add2(ap_ab, bsvd);
            pre_ab = fma2(dd_ab, wdd, pre_ab);
            pre_ab = fma2(ge_ab, wed, pre_ab);
            ull pre_cd = add2(ap_cd, bsvd);
            pre_cd = fma2(dd_cd, wdd, pre_cd);
            pre_cd = fma2(ge_cd, wed, pre_cd);
            ull s_ab = silu2t(pre_ab, HALF2);
            ull s_cd = silu2t(pre_cd, HALF2);
            const ulonglong2* q2 = (const ulonglong2*)(wsd + k*36);
            #pragma unroll
            for (int pp = 0; pp < 8; pp++){
                ulonglong2 qq = q2[pp];
                m_ab[2*pp]   = fma2(s_ab, qq.x, m_ab[2*pp]);
                m_ab[2*pp+1] = fma2(s_ab, qq.y, m_ab[2*pp+1]);
                m_cd[2*pp]   = fma2(s_cd, qq.x, m_cd[2*pp]);
                m_cd[2*pp+1] = fma2(s_cd, qq.y, m_cd[2*pp+1]);
            }
            {
                ull q16 = *(const ull*)(wsd + k*36 + 32);
                m_ab[16] = fma2(s_ab, q16, m_ab[16]);
                m_cd[16] = fma2(s_cd, q16, m_cd[16]);
            }
        }

        // me = exact silu(m), stays packed
        #pragma unroll
        for (int t = 0; t < MD; t++){ m_ab[t] = silu2x(m_ab[t]); m_cd[t] = silu2x(m_cd[t]); }

        // coor MLP packed; 4 hidden units per outer iter
        ull cw_ab = dup2(bc2v), cw_cd = cw_ab;
        #pragma unroll 1
        for (int h4 = 0; h4 < CHID/4; h4++){
            ull a0 = bc1u[4*h4], a1 = bc1u[4*h4+1], a2 = bc1u[4*h4+2], a3 = bc1u[4*h4+3];
            ull b0 = a0, b1 = a1, b2 = a2, b3 = a3;
            #pragma unroll
            for (int t = 0; t < MD; t++){
                float4 w4 = wc1f4[t*(CHID/4) + h4];
                ull w0 = dup2(w4.x), w1 = dup2(w4.y), w2 = dup2(w4.z), w3 = dup2(w4.w);
                a0 = fma2(m_ab[t], w0, a0); a1 = fma2(m_ab[t], w1, a1);
                a2 = fma2(m_ab[t], w2, a2); a3 = fma2(m_ab[t], w3, a3);
                b0 = fma2(m_cd[t], w0, b0); b1 = fma2(m_cd[t], w1, b1);
                b2 = fma2(m_cd[t], w2, b2); b3 = fma2(m_cd[t], w3, b3);
            }
            a0 = silu2x(a0); a1 = silu2x(a1); a2 = silu2x(a2); a3 = silu2x(a3);
            b0 = silu2x(b0); b1 = silu2x(b1); b2 = silu2x(b2); b3 = silu2x(b3);
            cw_ab = fma2(a0, wc2u[4*h4],   cw_ab);
            cw_ab = fma2(a1, wc2u[4*h4+1], cw_ab);
            cw_ab = fma2(a2, wc2u[4*h4+2], cw_ab);
            cw_ab = fma2(a3, wc2u[4*h4+3], cw_ab);
            cw_cd = fma2(b0, wc2u[4*h4],   cw_cd);
            cw_cd = fma2(b1, wc2u[4*h4+1], cw_cd);
            cw_cd = fma2(b2, wc2u[4*h4+2], cw_cd);
            cw_cd = fma2(b3, wc2u[4*h4+3], cw_cd);
        }

        float mask = jv ? 1.0f : 0.0f;
        ull mask2 = dup2(mask);

        // m_i reduction (packed rows)
        #pragma unroll
        for (int t = 0; t < MD; t++){
            ull v = mul2(m_ab[t], mask2);
            v = add2(v, shflx2(v, 16)); v = add2(v, shflx2(v, 8));
            v = add2(v, shflx2(v, 4));  v = add2(v, shflx2(v, 2));
            v = add2(v, shflx2(v, 1));
            ull w = mul2(m_cd[t], mask2);
            w = add2(w, shflx2(w, 16)); w = add2(w, shflx2(w, 8));
            w = add2(w, shflx2(w, 4));  w = add2(w, shflx2(w, 2));
            w = add2(w, shflx2(w, 1));
            if (lane == 0){
                float va, vb, vc, vd;
                unpk(v, va, vb); unpk(w, vc, vd);
                atomicAdd(&mi[ia*MD + t], va);
                if (iv1) atomicAdd(&mi[(ia+1)*MD + t], vb);
                if (iv2) atomicAdd(&mi[(ia+2)*MD + t], vc);
                if (iv3) atomicAdd(&mi[(ia+3)*MD + t], vd);
            }
        }

        // coor update reduction (packed rows)
        ull vx_ab = mul2(mul2(cw_ab, pk2(rx0, rx1)), mask2);
        ull vy_ab = mul2(mul2(cw_ab, pk2(ry0, ry1)), mask2);
        ull vz_ab = mul2(mul2(cw_ab, pk2(rz0, rz1)), mask2);
        ull vx_cd = mul2(mul2(cw_cd, pk2(rx2, rx3)), mask2);
        ull vy_cd = mul2(mul2(cw_cd, pk2(ry2, ry3)), mask2);
        ull vz_cd = mul2(mul2(cw_cd, pk2(rz2, rz3)), mask2);
        #pragma unroll
        for (int off = 16; off; off >>= 1){
            vx_ab = add2(vx_ab, shflx2(vx_ab, off));
            vy_ab = add2(vy_ab, shflx2(vy_ab, off));
            vz_ab = add2(vz_ab, shflx2(vz_ab, off));
            vx_cd = add2(vx_cd, shflx2(vx_cd, off));
            vy_cd = add2(vy_cd, shflx2(vy_cd, off));
            vz_cd = add2(vz_cd, shflx2(vz_cd, off));
        }
        if (lane == 0){
            float xa,xb,ya,yb,za,zb;
            unpk(vx_ab,xa,xb); unpk(vy_ab,ya,yb); unpk(vz_ab,za,zb);
            atomicAdd(&cnext[ia*3+0], xa); atomicAdd(&cnext[ia*3+1], ya); atomicAdd(&cnext[ia*3+2], za);
            if (iv1){ atomicAdd(&cnext[(ia+1)*3+0], xb); atomicAdd(&cnext[(ia+1)*3+1], yb); atomicAdd(&cnext[(ia+1)*3+2], zb); }
            unpk(vx_cd,xa,xb); unpk(vy_cd,ya,yb); unpk(vz_cd,za,zb);
            if (iv2){ atomicAdd(&cnext[(ia+2)*3+0], xa); atomicAdd(&cnext[(ia+2)*3+1], ya); atomicAdd(&cnext[(ia+2)*3+2], za); }
            if (iv3){ atomicAdd(&cnext[(ia+3)*3+0], xb); atomicAdd(&cnext[(ia+3)*3+1], yb); atomicAdd(&cnext[(ia+3)*3+2], zb); }
        }
    }
}

// ---------------- node MLP + next-layer A/B (all 3 pools) ----------------
__global__ void k_nodeAB(const float* __restrict__ Wn1L, const float* __restrict__ bn1L,
                         const float* __restrict__ Wn2L, const float* __restrict__ bn2L,
                         const float* __restrict__ We1N, const float* __restrict__ be1N,
                         int do_ab, int flag_next){
    __shared__ float in[81];
    __shared__ float z[128];
    __shared__ float hnew[DIMF];
    int p, i, n; pool_of(blockIdx.x, p, i, n);
    (void)n;
    int tid = threadIdx.x;
    float* hc = g_hc + p*NMAX*DIMF + i*DIMF;
    float* miP = g_mi + p*NMAX*MD + i*MD;
    if (tid < DIMF) in[tid] = hc[tid];
    else if (tid < 81) in[tid] = miP[tid - DIMF];
    __syncthreads();
    if (tid < 128){
        float acc = bn1L[tid];
        #pragma unroll 1
        for (int k = 0; k < 81; k++) acc = fmaf(in[k], Wn1L[k*128 + tid], acc);
        z[tid] = siluf(acc);
    }
    __syncthreads();
    if (tid < DIMF){
        float a2 = bn2L[tid];
        #pragma unroll 1
        for (int k = 0; k < 128; k++) a2 = fmaf(z[k], Wn2L[k*DIMF + tid], a2);
        float v = fmaxf(2.0f*in[tid] + a2, 0.0f);
        hnew[tid] = v;
        hc[tid] = v;
    }
    if (!do_ab) return;
    if (tid >= DIMF && tid < DIMF + MD) miP[tid - DIMF] = 0.0f;
    else if (tid >= DIMF + MD && tid < DIMF + MD + 3){
        int c = tid - DIMF - MD;
        float* cn = (flag_next ? g_cA : g_cB) + p*NMAX*3;
        const float* cc = (flag_next ? g_cB : g_cA) + p*NMAX*3;
        cn[i*3 + c] = cc[i*3 + c];
    }
    __syncthreads();
    float* Ar = g_Arow + p*NMAX*H1 + i*H1;
    float* Br = g_Brow + p*NMAX*H1 + i*H1;
    for (int k = tid; k < H1; k += 256){
        float a = be1N[k], b = 0.0f;
        #pragma unroll
        for (int d = 0; d < DIMF; d++){
            a = fmaf(hnew[d], We1N[d*H1 + k], a);
            b = fmaf(hnew[d], We1N[(DIMF + d)*H1 + k], b);
        }
        Ar[k] = a;
        Br[k] = b;
    }
}

// ---------------- final scatter with max-merge (values >= 0) ----------------
__global__ void k_scatter(float* out){
    int p, i, n; pool_of(blockIdx.x, p, i, n);
    (void)n;
    int t = threadIdx.x;
    int a = g_idx[p*NFULL + i];
    float v = g_hc[p*NMAX*DIMF + i*DIMF + t];
    atomicMax((int*)&out[a*DIMF + t], __float_as_int(v));
}

// ---------------- host ----------------
extern "C" void kernel_launch(void* const* d_in, const int* in_sizes, int n_in,
                              void* d_out, int out_size){
    const float* feat = (const float*)d_in[0];
    const float* coor = (const float*)d_in[1];
    const float* edge = (const float*)d_in[2];
    const float* We1  = (const float*)d_in[3];
    const float* be1  = (const float*)d_in[4];
    const float* We2  = (const float*)d_in[5];
    const float* be2  = (const float*)d_in[6];
    const float* Wc1  = (const float*)d_in[7];
    const float* bc1  = (const float*)d_in[8];
    const float* Wc2  = (const float*)d_in[9];
    const float* bc2  = (const float*)d_in[10];
    const float* Wn1  = (const float*)d_in[11];
    const float* bn1  = (const float*)d_in[12];
    const float* Wn2  = (const float*)d_in[13];
    const float* bn2  = (const float*)d_in[14];
    const float* wp   = (const float*)d_in[15];
    const float* bp   = (const float*)d_in[16];
    float* out = (float*)d_out;

    const int EDGE_SMEM = 28340 * 4;   // 113360 B
    cudaFuncSetAttribute(k_edge, cudaFuncAttributeMaxDynamicSharedMemorySize, EDGE_SMEM);

    k_zero_out<<<128, 256>>>(out);                      // 0
    k_ugbits_scores<<<512, 512>>>(edge, feat, wp, bp);  // 1
    k_ug2<<<512, 32>>>();                               // 2
    k_rank<<<dim3(NFULL, 3), 128>>>();                  // 3
    k_prep<<<NTOT, 256>>>(feat, coor, We1, be1);        // 4
    for (int l = 0; l < 3; l++){
        k_edge<<<EGRID, 256, EDGE_SMEM>>>(l & 1,        // 5, 7, 9
            We1 + l*130*H1, We2 + l*H1*MD, be2 + l*MD,
            Wc1 + l*MD*CHID, bc1 + l*CHID, Wc2 + l*CHID, bc2 + l);
        int ln = (l < 2) ? (l + 1) : 2;
        k_nodeAB<<<NTOT, 256>>>(                        // 6, 8, 10
            Wn1 + l*81*128, bn1 + l*128, Wn2 + l*128*DIMF, bn2 + l*DIMF,
            We1 + ln*130*H1, be1 + ln*H1,
            (l < 2) ? 1 : 0, (l + 1) & 1);
    }
    k_scatter<<<NTOT, 64>>>(out);                       // 11
}

// round 8
// speedup vs baseline: 1.9234x; 1.1196x over previous
#include <cuda_runtime.h>
#include <stdint.h>

#define NFULL 512
#define DIMF  64
#define H1    260
#define MD    17
#define CHID  68
#define NMAX  460
#define N0 460
#define N1 358
#define N2 307
#define NTOT 1125
// edge grid: gx {23,18,16} x nspl {6,5,4} -> {138,90,64} = 292 blocks (one wave @2/SM)
#define EGRID 292
#define RPB   20   // rows per block (10 warps x 2 rows)

typedef unsigned long long ull;

// ---------------- device scratch (per-pool batched) ----------------
__device__ uint32_t g_ugbits[NFULL*16];
__device__ uint32_t g_ug2bits[NFULL*16];
__device__ float    g_scores[3*NFULL];
__device__ int      g_idx[3*NFULL];
__device__ uint32_t g_gsub[3*NMAX*16];
__device__ float    g_hc[3*NMAX*DIMF];
__device__ float    g_cA[3*NMAX*3];
__device__ float    g_cB[3*NMAX*3];
__device__ float    g_Arow[3*NMAX*H1];
__device__ float    g_Brow[3*NMAX*H1];
__device__ float    g_mi[3*NMAX*MD];

// ---------------- helpers ----------------
__device__ __forceinline__ float ex2a(float x){ float y; asm("ex2.approx.ftz.f32 %0, %1;" : "=f"(y) : "f"(x)); return y; }
__device__ __forceinline__ float rcpa(float x){ float y; asm("rcp.approx.ftz.f32 %0, %1;" : "=f"(y) : "f"(x)); return y; }
__device__ __forceinline__ float tanha(float x){ float y; asm("tanh.approx.f32 %0, %1;" : "=f"(y) : "f"(x)); return y; }
__device__ __forceinline__ float siluf(float x){
    return x * rcpa(1.0f + ex2a(-1.4426950408889634f * x));
}
__device__ __forceinline__ float sigf(float x){
    return rcpa(1.0f + ex2a(-1.4426950408889634f * x));
}
__device__ __forceinline__ ull pk2(float lo, float hi){
    ull r; asm("mov.b64 %0, {%1,%2};" : "=l"(r) : "r"(__float_as_uint(lo)), "r"(__float_as_uint(hi))); return r;
}
__device__ __forceinline__ ull dup2(float v){
    ull r; asm("mov.b64 %0, {%1,%1};" : "=l"(r) : "r"(__float_as_uint(v))); return r;
}
__device__ __forceinline__ void unpk(ull v, float& lo, float& hi){
    unsigned a, b;
    asm("mov.b64 {%0,%1}, %2;" : "=r"(a), "=r"(b) : "l"(v));
    lo = __uint_as_float(a); hi = __uint_as_float(b);
}
__device__ __forceinline__ ull fma2(ull a, ull b, ull c){
    ull d; asm("fma.rn.f32x2 %0, %1, %2, %3;" : "=l"(d) : "l"(a), "l"(b), "l"(c)); return d;
}
__device__ __forceinline__ ull add2(ull a, ull b){
    ull d; asm("add.rn.f32x2 %0, %1, %2;" : "=l"(d) : "l"(a), "l"(b)); return d;
}
__device__ __forceinline__ ull mul2(ull a, ull b){
    ull d; asm("mul.rn.f32x2 %0, %1, %2;" : "=l"(d) : "l"(a), "l"(b)); return d;
}
// fast packed silu via tanh: silu(x) = h + h*tanh(h), h = x/2
__device__ __forceinline__ ull silu2t(ull x, ull HALF2){
    ull h = mul2(x, HALF2);
    float h0, h1; unpk(h, h0, h1);
    ull t = pk2(tanha(h0), tanha(h1));
    return fma2(h, t, h);
}
// exact packed silu (epilogue)
__device__ __forceinline__ ull silu2x(ull x){
    ull t = mul2(x, dup2(-1.4426950408889634f));
    float t0, t1; unpk(t, t0, t1);
    ull e = add2(pk2(ex2a(t0), ex2a(t1)), dup2(1.0f));
    float u0, u1; unpk(e, u0, u1);
    return mul2(x, pk2(rcpa(u0), rcpa(u1)));
}
__device__ __forceinline__ ull shflx2(ull v, int off){
    float lo, hi; unpk(v, lo, hi);
    lo = __shfl_xor_sync(0xffffffffu, lo, off);
    hi = __shfl_xor_sync(0xffffffffu, hi, off);
    return pk2(lo, hi);
}
__device__ __forceinline__ void pool_of(int bid, int& p, int& i, int& n){
    if (bid < N0){ p = 0; i = bid; n = N0; }
    else if (bid < N0+N1){ p = 1; i = bid - N0; n = N1; }
    else { p = 2; i = bid - N0 - N1; n = N2; }
}

// ---------------- launch 0: zero output ----------------
__global__ void k_zero_out(float* out){
    int t = blockIdx.x*blockDim.x + threadIdx.x;
    if (t < NFULL*DIMF) out[t] = 0.0f;
}

// ---------------- launch 1: adjacency bits + pool scores ----------------
__global__ void k_ugbits_scores(const float* __restrict__ edge, const float* __restrict__ feat,
                                const float* __restrict__ wp, const float* __restrict__ bp){
    int a = blockIdx.x, tid = threadIdx.x, lane = tid & 31, w = tid >> 5;
    bool b = edge[a*NFULL + tid] != 0.0f;
    unsigned m = __ballot_sync(0xffffffffu, b);
    if (lane == 0) g_ugbits[a*16 + w] = m;
    if (w < 3){
        float v = feat[a*DIMF + lane]*wp[w*DIMF + lane]
                + feat[a*DIMF + 32 + lane]*wp[w*DIMF + 32 + lane];
        for (int off = 16; off; off >>= 1) v += __shfl_xor_sync(0xffffffffu, v, off);
        if (lane == 0) g_scores[w*NFULL + a] = sigf(v + bp[w]);
    }
}

// ---------------- launch 2: ug2 = (ug@ug != 0) ----------------
__global__ void k_ug2(){
    __shared__ uint32_t row[16];
    int a = blockIdx.x, lane = threadIdx.x;
    if (lane < 16) row[lane] = g_ugbits[a*16 + lane];
    __syncwarp();
    uint32_t acc = 0;
    for (int c = 0; c < NFULL; c++){
        if ((row[c>>5] >> (c&31)) & 1u){
            if (lane < 16) acc |= g_ugbits[c*16 + lane];
        }
    }
    if (lane < 16) g_ug2bits[a*16 + lane] = acc;
}

// ---------------- launch 3: rank -> compacted slot (all 3 pools) ----------------
__global__ void k_rank(){
    __shared__ int ired[4];
    int p = blockIdx.y, a = blockIdx.x;
    int kcnt = (p == 0) ? N0 : (p == 1) ? N1 : N2;
    const float* sc = g_scores + p*NFULL;
    float s = sc[a];
    int tid = threadIdx.x, lane = tid & 31, w = tid >> 5;
    int r = 0;
    for (int b = tid; b < NFULL; b += 128){
        float sb = sc[b];
        r += (sb > s) || (sb == s && b < a);
    }
    for (int off = 16; off; off >>= 1) r += __shfl_xor_sync(0xffffffffu, r, off);
    if (lane == 0) ired[w] = r;
    __syncthreads();
    if (tid == 0){
        int rt = ired[0] + ired[1] + ired[2] + ired[3];
        if (rt < kcnt) g_idx[p*NFULL + rt] = a;
    }
}

// ---------------- launch 4: prep = gather + gsub + layer0 A/B + inits ----------------
__global__ void k_prep(const float* __restrict__ feat, const float* __restrict__ coor,
                       const float* __restrict__ We1, const float* __restrict__ be1){
    __shared__ float h[DIMF];
    int p, i, n; pool_of(blockIdx.x, p, i, n);
    const int* idx = g_idx + p*NFULL;
    int a = idx[i];
    int tid = threadIdx.x, lane = tid & 31;
    float s = g_scores[p*NFULL + a];
    if (tid < DIMF){
        float v = feat[a*DIMF + tid] * s;
        h[tid] = v;
        g_hc[p*NMAX*DIMF + i*DIMF + tid] = v;
    } else if (tid < DIMF + 3){
        int c = tid - DIMF;
        float cv = coor[a*3 + c];
        g_cA[p*NMAX*3 + i*3 + c] = cv;
        g_cB[p*NMAX*3 + i*3 + c] = cv;
    } else if (tid < DIMF + 3 + MD){
        g_mi[p*NMAX*MD + i*MD + (tid - DIMF - 3)] = 0.0f;
    } else if (tid >= 128){
        int w = (tid >> 5) - 4;  // 0..3, full warps
        for (int q = 0; q < 4; q++){
            int wd = w*4 + q, j = wd*32 + lane;
            bool bit = false;
            if (j < n){
                int gj = idx[j];
                bit = (g_ug2bits[a*16 + (gj>>5)] >> (gj&31)) & 1u;
            }
            unsigned m = __ballot_sync(0xffffffffu, bit);
            if (lane == 0) g_gsub[p*NMAX*16 + i*16 + wd] = m;
        }
    }
    __syncthreads();
    float* Ar = g_Arow + p*NMAX*H1 + i*H1;
    float* Br = g_Brow + p*NMAX*H1 + i*H1;
    for (int k = tid; k < H1; k += 256){
        float av = be1[k], bv = 0.0f;
        #pragma unroll
        for (int d = 0; d < DIMF; d++){
            av = fmaf(h[d], We1[d*H1 + k], av);
            bv = fmaf(h[d], We1[(DIMF + d)*H1 + k], bv);
        }
        Ar[k] = av;
        Br[k] = bv;
    }
}

// ---------------- the heavy edge kernel (all 3 pools, 10 warps x 2 rows) ----------------
__global__ void __launch_bounds__(320, 2) k_edge(int flag,
    const float* __restrict__ We1L, const float* __restrict__ We2L,
    const float* __restrict__ be2L, const float* __restrict__ Wc1L,
    const float* __restrict__ bc1L, const float* __restrict__ Wc2L,
    const float* __restrict__ bc2L)
{
    extern __shared__ float sm[];
    float* ws   = sm;               // 260*20: We2 k-rows, t-linear (17 used + 3 zero)
    float* Bs   = ws + 5200;        // 260*33: B tile, k-major, conflict-free
    float* As2  = Bs + 8580;        // 260*20: A tile, k-major, 20 rows
    float* wded = As2 + 5200;       // 260*4: (wd,wd,we,we) -> one LDS.128
    float* wc1d = wded + 1040;      // 17*136: Wc1 duplicated pairs
    float* bc1d = wc1d + 2312;      // 136 (duplicated)
    float* wc2d = bc1d + 136;       // 136 (duplicated)
    float* be2p = wc2d + 136;       // 20 (t-linear, 17 used + 3 zero)
    float* cj   = be2p + 20;        // 96
    float* bc2s = cj + 96;          // 4  -> 22724 floats = 90896 B

    // pool decode
    int bid = blockIdx.x, p, lb, gx, nspl, n, nch;
    if (bid < 138){ p = 0; lb = bid;       gx = 23; nspl = 6; n = N0; nch = 15; }
    else if (bid < 228){ p = 1; lb = bid - 138; gx = 18; nspl = 5; n = N1; nch = 12; }
    else { p = 2; lb = bid - 228; gx = 16; nspl = 4; n = N2; nch = 10; }
    int bx = lb % gx, by = lb / gx;

    const float* Arow = g_Arow + p*NMAX*H1;
    const float* Brow = g_Brow + p*NMAX*H1;
    const uint32_t* gsub = g_gsub + p*NMAX*16;
    float* mi = g_mi + p*NMAX*MD;
    const float* ccur = (flag ? g_cB : g_cA) + p*NMAX*3;
    float*       cnext = (flag ? g_cA : g_cB) + p*NMAX*3;

    int tid = threadIdx.x, lane = tid & 31, wi = tid >> 5;
    const ull HALF2 = dup2(0.5f);

    // ---- stage weights ----
    for (int t = tid; t < 5200; t += 320){
        int k = t / 20, c = t - 20*k;
        ws[t] = (c < MD) ? We2L[k*MD + c] : 0.0f;
    }
    for (int t = tid; t < H1; t += 320){
        float wd = We1L[128*H1 + t], we = We1L[129*H1 + t];
        wded[4*t+0] = wd; wded[4*t+1] = wd; wded[4*t+2] = we; wded[4*t+3] = we;
    }
    for (int e = tid; e < MD*CHID; e += 320){
        int t = e / CHID, h = e - t*CHID;
        float v = Wc1L[e];
        wc1d[t*136 + 2*h] = v; wc1d[t*136 + 2*h + 1] = v;
    }
    if (tid < CHID){
        float v1 = bc1L[tid]; bc1d[2*tid] = v1; bc1d[2*tid+1] = v1;
        float v2 = Wc2L[tid]; wc2d[2*tid] = v2; wc2d[2*tid+1] = v2;
    }
    if (tid < 20) be2p[tid] = (tid < MD) ? be2L[tid] : 0.0f;
    if (tid == 0) bc2s[0] = bc2L[0];

    // ---- stage A tile (20 rows) ----
    int i0 = bx * RPB;
    for (int e = tid; e < RPB*H1; e += 320){
        int r = e / H1, k = e - r*H1;
        int ii = i0 + r;
        As2[k*RPB + r] = (ii < n) ? Arow[ii*H1 + k] : 0.0f;
    }
    __syncthreads();
    const float bc2v = bc2s[0];

    int ia = i0 + 2*wi, ib = ia + 1;
    bool iv0 = (ia < n), iv1 = (ib < n);
    float c0x=0,c0y=0,c0z=0,c1x=0,c1y=0,c1z=0;
    if (iv0){ c0x=ccur[ia*3];  c0y=ccur[ia*3+1];  c0z=ccur[ia*3+2]; }
    if (iv1){ c1x=ccur[ib*3];  c1y=ccur[ib*3+1];  c1z=ccur[ib*3+2]; }

    const ull* bc1u = (const ull*)bc1d;
    const ull* wc2u = (const ull*)wc2d;

    for (int ch = by; ch < nch; ch += nspl){
        int j0 = ch << 5;
        __syncthreads();
        for (int e = tid; e < 32*H1; e += 320){
            int jj = e / H1, k = e - jj*H1;
            int j = j0 + jj;
            Bs[k*33 + jj] = (j < n) ? Brow[j*H1 + k] : 0.0f;
        }
        for (int t = tid; t < 96; t += 320){
            int c = t / 32, jj = t - c*32;
            int j = j0 + jj;
            cj[t] = (j < n) ? ccur[j*3 + c] : 0.0f;
        }
        __syncthreads();
        if (!iv0) continue;   // staging/syncs above run unconditionally

        int j = j0 + lane;
        bool jv = (j < n);
        float jx = cj[lane], jy = cj[32+lane], jz = cj[64+lane];
        float r0x=c0x-jx, r0y=c0y-jy, r0z=c0z-jz;
        float r1x=c1x-jx, r1y=c1y-jy, r1z=c1z-jz;
        ull dd01 = pk2(r0x*r0x+r0y*r0y+r0z*r0z, r1x*r1x+r1y*r1y+r1z*r1z);
        uint32_t gb0 = iv0 ? gsub[ia*16 + ch] : 0u;
        uint32_t gb1 = iv1 ? gsub[ib*16 + ch] : 0u;
        ull ge01 = pk2(((gb0>>lane)&1u)?1.0f:0.0f, ((gb1>>lane)&1u)?1.0f:0.0f);

        // t-packed accumulators: m_a (row ia), m_b (row ib), 9 pairs each
        ull m_a[9], m_b[9];
        const ull* be2u = (const ull*)be2p;
        #pragma unroll
        for (int tp = 0; tp < 9; tp++){ m_a[tp] = be2u[tp]; m_b[tp] = m_a[tp]; }

        #pragma unroll 4
        for (int k = 0; k < H1; k++){
            ull ap = *(const ull*)(As2 + k*RPB + 2*wi);          // (A_ia, A_ib)
            ulonglong2 ww = *(const ulonglong2*)(wded + (k<<2)); // ((wd,wd),(we,we))
            ull bsvd = dup2(Bs[k*33 + lane]);
            ull pre = add2(ap, bsvd);
            pre = fma2(dd01, ww.x, pre);
            pre = fma2(ge01, ww.y, pre);
            ull s01 = silu2t(pre, HALF2);
            float s0, s1; unpk(s01, s0, s1);
            ull s0d = dup2(s0), s1d = dup2(s1);
            const ulonglong2* q2 = (const ulonglong2*)(ws + k*20);
            #pragma unroll
            for (int pp = 0; pp < 4; pp++){
                ulonglong2 qq = q2[pp];
                m_a[2*pp]   = fma2(s0d, qq.x, m_a[2*pp]);
                m_a[2*pp+1] = fma2(s0d, qq.y, m_a[2*pp+1]);
                m_b[2*pp]   = fma2(s1d, qq.x, m_b[2*pp]);
                m_b[2*pp+1] = fma2(s1d, qq.y, m_b[2*pp+1]);
            }
            {
                ull q8 = *(const ull*)(ws + k*20 + 16);
                m_a[8] = fma2(s0d, q8, m_a[8]);
                m_b[8] = fma2(s1d, q8, m_b[8]);
            }
        }

        // unpack t-pairs -> exact silu -> repack as row-pairs me01[t] = (me_ia, me_ib)
        ull me01[MD];
        #pragma unroll
        for (int tp = 0; tp < 9; tp++){
            float a0, a1, b0, b1;
            unpk(m_a[tp], a0, a1); unpk(m_b[tp], b0, b1);
            me01[2*tp] = silu2x(pk2(a0, b0));
            if (2*tp + 1 < MD) me01[2*tp+1] = silu2x(pk2(a1, b1));
        }

        // coor MLP, row-pair packed, 2 hidden units per iter
        ull cw01 = dup2(bc2v);
        #pragma unroll 2
        for (int h2 = 0; h2 < CHID/2; h2++){
            ull a0 = bc1u[2*h2], a1 = bc1u[2*h2+1];
            #pragma unroll
            for (int t = 0; t < MD; t++){
                ulonglong2 wwp = ((const ulonglong2*)(wc1d + t*136))[h2];
                a0 = fma2(me01[t], wwp.x, a0);
                a1 = fma2(me01[t], wwp.y, a1);
            }
            a0 = silu2x(a0); a1 = silu2x(a1);
            cw01 = fma2(a0, wc2u[2*h2],   cw01);
            cw01 = fma2(a1, wc2u[2*h2+1], cw01);
        }

        float mask = jv ? 1.0f : 0.0f;
        ull mask2 = dup2(mask);

        // m_i reduction (row-pair packed)
        #pragma unroll
        for (int t = 0; t < MD; t++){
            ull v = mul2(me01[t], mask2);
            v = add2(v, shflx2(v, 16)); v = add2(v, shflx2(v, 8));
            v = add2(v, shflx2(v, 4));  v = add2(v, shflx2(v, 2));
            v = add2(v, shflx2(v, 1));
            if (lane == 0){
                float va, vb; unpk(v, va, vb);
                atomicAdd(&mi[ia*MD + t], va);
                if (iv1) atomicAdd(&mi[ib*MD + t], vb);
            }
        }

        // coor update reduction (row-pair packed)
        ull vx = mul2(mul2(cw01, pk2(r0x, r1x)), mask2);
        ull vy = mul2(mul2(cw01, pk2(r0y, r1y)), mask2);
        ull vz = mul2(mul2(cw01, pk2(r0z, r1z)), mask2);
        #pragma unroll
        for (int off = 16; off; off >>= 1){
            vx = add2(vx, shflx2(vx, off));
            vy = add2(vy, shflx2(vy, off));
            vz = add2(vz, shflx2(vz, off));
        }
        if (lane == 0){
            float xa,xb,ya,yb,za,zb;
            unpk(vx,xa,xb); unpk(vy,ya,yb); unpk(vz,za,zb);
            atomicAdd(&cnext[ia*3+0], xa); atomicAdd(&cnext[ia*3+1], ya); atomicAdd(&cnext[ia*3+2], za);
            if (iv1){ atomicAdd(&cnext[ib*3+0], xb); atomicAdd(&cnext[ib*3+1], yb); atomicAdd(&cnext[ib*3+2], zb); }
        }
    }
}

// ---------------- node MLP + next-layer A/B (all 3 pools) ----------------
__global__ void k_nodeAB(const float* __restrict__ Wn1L, const float* __restrict__ bn1L,
                         const float* __restrict__ Wn2L, const float* __restrict__ bn2L,
                         const float* __restrict__ We1N, const float* __restrict__ be1N,
                         int do_ab, int flag_next){
    __shared__ float in[81];
    __shared__ float z[128];
    __shared__ float hnew[DIMF];
    int p, i, n; pool_of(blockIdx.x, p, i, n);
    (void)n;
    int tid = threadIdx.x;
    float* hc = g_hc + p*NMAX*DIMF + i*DIMF;
    float* miP = g_mi + p*NMAX*MD + i*MD;
    if (tid < DIMF) in[tid] = hc[tid];
    else if (tid < 81) in[tid] = miP[tid - DIMF];
    __syncthreads();
    if (tid < 128){
        float acc = bn1L[tid];
        #pragma unroll 1
        for (int k = 0; k < 81; k++) acc = fmaf(in[k], Wn1L[k*128 + tid], acc);
        z[tid] = siluf(acc);
    }
    __syncthreads();
    if (tid < DIMF){
        float a2 = bn2L[tid];
        #pragma unroll 1
        for (int k = 0; k < 128; k++) a2 = fmaf(z[k], Wn2L[k*DIMF + tid], a2);
        float v = fmaxf(2.0f*in[tid] + a2, 0.0f);
        hnew[tid] = v;
        hc[tid] = v;
    }
    if (!do_ab) return;
    if (tid >= DIMF && tid < DIMF + MD) miP[tid - DIMF] = 0.0f;
    else if (tid >= DIMF + MD && tid < DIMF + MD + 3){
        int c = tid - DIMF - MD;
        float* cn = (flag_next ? g_cA : g_cB) + p*NMAX*3;
        const float* cc = (flag_next ? g_cB : g_cA) + p*NMAX*3;
        cn[i*3 + c] = cc[i*3 + c];
    }
    __syncthreads();
    float* Ar = g_Arow + p*NMAX*H1 + i*H1;
    float* Br = g_Brow + p*NMAX*H1 + i*H1;
    for (int k = tid; k < H1; k += 256){
        float a = be1N[k], b = 0.0f;
        #pragma unroll
        for (int d = 0; d < DIMF; d++){
            a = fmaf(hnew[d], We1N[d*H1 + k], a);
            b = fmaf(hnew[d], We1N[(DIMF + d)*H1 + k], b);
        }
        Ar[k] = a;
        Br[k] = b;
    }
}

// ---------------- final scatter with max-merge (values >= 0) ----------------
__global__ void k_scatter(float* out){
    int p, i, n; pool_of(blockIdx.x, p, i, n);
    (void)n;
    int t = threadIdx.x;
    int a = g_idx[p*NFULL + i];
    float v = g_hc[p*NMAX*DIMF + i*DIMF + t];
    atomicMax((int*)&out[a*DIMF + t], __float_as_int(v));
}

// ---------------- host ----------------
extern "C" void kernel_launch(void* const* d_in, const int* in_sizes, int n_in,
                              void* d_out, int out_size){
    const float* feat = (const float*)d_in[0];
    const float* coor = (const float*)d_in[1];
    const float* edge = (const float*)d_in[2];
    const float* We1  = (const float*)d_in[3];
    const float* be1  = (const float*)d_in[4];
    const float* We2  = (const float*)d_in[5];
    const float* be2  = (const float*)d_in[6];
    const float* Wc1  = (const float*)d_in[7];
    const float* bc1  = (const float*)d_in[8];
    const float* Wc2  = (const float*)d_in[9];
    const float* bc2  = (const float*)d_in[10];
    const float* Wn1  = (const float*)d_in[11];
    const float* bn1  = (const float*)d_in[12];
    const float* Wn2  = (const float*)d_in[13];
    const float* bn2  = (const float*)d_in[14];
    const float* wp   = (const float*)d_in[15];
    const float* bp   = (const float*)d_in[16];
    float* out = (float*)d_out;

    const int EDGE_SMEM = 22724 * 4;   // 90896 B
    cudaFuncSetAttribute(k_edge, cudaFuncAttributeMaxDynamicSharedMemorySize, EDGE_SMEM);

    k_zero_out<<<128, 256>>>(out);                      // 0
    k_ugbits_scores<<<512, 512>>>(edge, feat, wp, bp);  // 1
    k_ug2<<<512, 32>>>();                               // 2
    k_rank<<<dim3(NFULL, 3), 128>>>();                  // 3
    k_prep<<<NTOT, 256>>>(feat, coor, We1, be1);        // 4
    for (int l = 0; l < 3; l++){
        k_edge<<<EGRID, 320, EDGE_SMEM>>>(l & 1,        // 5, 7, 9
            We1 + l*130*H1, We2 + l*H1*MD, be2 + l*MD,
            Wc1 + l*MD*CHID, bc1 + l*CHID, Wc2 + l*CHID, bc2 + l);
        int ln = (l < 2) ? (l + 1) : 2;
        k_nodeAB<<<NTOT, 256>>>(                        // 6, 8, 10
            Wn1 + l*81*128, bn1 + l*128, Wn2 + l*128*DIMF, bn2 + l*DIMF,
            We1 + ln*130*H1, be1 + ln*H1,
            (l < 2) ? 1 : 0, (l + 1) & 1);
    }
    k_scatter<<<NTOT, 64>>>(out);                       // 11
}

// round 9
// speedup vs baseline: 1.9899x; 1.0346x over previous
#include <cuda_runtime.h>
#include <stdint.h>

#define NFULL 512
#define DIMF  64
#define H1    260
#define MD    17
#define CHID  68
#define NMAX  460
#define N0 460
#define N1 358
#define N2 307
#define NTOT 1125
// edge grid: gx {20,15,13} x nspl {7,6,5} -> {140,90,65} = 295 blocks (one wave @2/SM)
#define EGRID 295
#define RPB   24   // rows per block (12 warps x 2 rows)
#define ETHR  384

typedef unsigned long long ull;

// ---------------- device scratch (per-pool batched) ----------------
__device__ uint32_t g_ugbits[NFULL*16];
__device__ uint32_t g_ug2bits[NFULL*16];
__device__ float    g_scores[3*NFULL];
__device__ int      g_idx[3*NFULL];
__device__ uint32_t g_gsub[3*NMAX*16];
__device__ float    g_hc[3*NMAX*DIMF];
__device__ float    g_cA[3*NMAX*3];
__device__ float    g_cB[3*NMAX*3];
__device__ float    g_Arow[3*NMAX*H1];
__device__ float    g_Brow[3*NMAX*H1];
__device__ float    g_mi[3*NMAX*MD];

// ---------------- helpers ----------------
__device__ __forceinline__ float ex2a(float x){ float y; asm("ex2.approx.ftz.f32 %0, %1;" : "=f"(y) : "f"(x)); return y; }
__device__ __forceinline__ float rcpa(float x){ float y; asm("rcp.approx.ftz.f32 %0, %1;" : "=f"(y) : "f"(x)); return y; }
__device__ __forceinline__ float tanha(float x){ float y; asm("tanh.approx.f32 %0, %1;" : "=f"(y) : "f"(x)); return y; }
__device__ __forceinline__ float siluf(float x){
    return x * rcpa(1.0f + ex2a(-1.4426950408889634f * x));
}
__device__ __forceinline__ float sigf(float x){
    return rcpa(1.0f + ex2a(-1.4426950408889634f * x));
}
__device__ __forceinline__ ull pk2(float lo, float hi){
    ull r; asm("mov.b64 %0, {%1,%2};" : "=l"(r) : "r"(__float_as_uint(lo)), "r"(__float_as_uint(hi))); return r;
}
__device__ __forceinline__ ull dup2(float v){
    ull r; asm("mov.b64 %0, {%1,%1};" : "=l"(r) : "r"(__float_as_uint(v))); return r;
}
__device__ __forceinline__ void unpk(ull v, float& lo, float& hi){
    unsigned a, b;
    asm("mov.b64 {%0,%1}, %2;" : "=r"(a), "=r"(b) : "l"(v));
    lo = __uint_as_float(a); hi = __uint_as_float(b);
}
__device__ __forceinline__ ull fma2(ull a, ull b, ull c){
    ull d; asm("fma.rn.f32x2 %0, %1, %2, %3;" : "=l"(d) : "l"(a), "l"(b), "l"(c)); return d;
}
__device__ __forceinline__ ull add2(ull a, ull b){
    ull d; asm("add.rn.f32x2 %0, %1, %2;" : "=l"(d) : "l"(a), "l"(b)); return d;
}
__device__ __forceinline__ ull mul2(ull a, ull b){
    ull d; asm("mul.rn.f32x2 %0, %1, %2;" : "=l"(d) : "l"(a), "l"(b)); return d;
}
// fast packed silu via tanh: silu(x) = h + h*tanh(h), h = x/2
__device__ __forceinline__ ull silu2t(ull x, ull HALF2){
    ull h = mul2(x, HALF2);
    float h0, h1; unpk(h, h0, h1);
    ull t = pk2(tanha(h0), tanha(h1));
    return fma2(h, t, h);
}
// exact packed silu (epilogue)
__device__ __forceinline__ ull silu2x(ull x){
    ull t = mul2(x, dup2(-1.4426950408889634f));
    float t0, t1; unpk(t, t0, t1);
    ull e = add2(pk2(ex2a(t0), ex2a(t1)), dup2(1.0f));
    float u0, u1; unpk(e, u0, u1);
    return mul2(x, pk2(rcpa(u0), rcpa(u1)));
}
__device__ __forceinline__ ull shflx2(ull v, int off){
    float lo, hi; unpk(v, lo, hi);
    lo = __shfl_xor_sync(0xffffffffu, lo, off);
    hi = __shfl_xor_sync(0xffffffffu, hi, off);
    return pk2(lo, hi);
}
__device__ __forceinline__ void pool_of(int bid, int& p, int& i, int& n){
    if (bid < N0){ p = 0; i = bid; n = N0; }
    else if (bid < N0+N1){ p = 1; i = bid - N0; n = N1; }
    else { p = 2; i = bid - N0 - N1; n = N2; }
}

// ---------------- launch 4: zero output ----------------
__global__ void k_zero_out(float* out){
    int t = blockIdx.x*blockDim.x + threadIdx.x;
    if (t < NFULL*DIMF) out[t] = 0.0f;
}

// ---------------- launch 0: adjacency bits + pool scores ----------------
__global__ void k_ugbits_scores(const float* __restrict__ edge, const float* __restrict__ feat,
                                const float* __restrict__ wp, const float* __restrict__ bp){
    int a = blockIdx.x, tid = threadIdx.x, lane = tid & 31, w = tid >> 5;
    bool b = edge[a*NFULL + tid] != 0.0f;
    unsigned m = __ballot_sync(0xffffffffu, b);
    if (lane == 0) g_ugbits[a*16 + w] = m;
    if (w < 3){
        float v = feat[a*DIMF + lane]*wp[w*DIMF + lane]
                + feat[a*DIMF + 32 + lane]*wp[w*DIMF + 32 + lane];
        for (int off = 16; off; off >>= 1) v += __shfl_xor_sync(0xffffffffu, v, off);
        if (lane == 0) g_scores[w*NFULL + a] = sigf(v + bp[w]);
    }
}

// ---------------- launch 1: fused ug2 (y=0) + rank (y=1..3) ----------------
__global__ void k_ug2rank(){
    int tid = threadIdx.x, lane = tid & 31, w = tid >> 5;
    int a = blockIdx.x;
    if (blockIdx.y == 0){
        // ug2 = (ug@ug != 0) for node a; 4 warps split the c-range
        __shared__ uint32_t row[16];
        __shared__ uint32_t accs[4][16];
        if (tid < 16) row[tid] = g_ugbits[a*16 + tid];
        __syncthreads();
        uint32_t acc = 0;
        int c0 = w*128;
        for (int c = c0; c < c0 + 128; c++){
            if ((row[c>>5] >> (c&31)) & 1u){
                if (lane < 16) acc |= g_ugbits[c*16 + lane];
            }
        }
        if (lane < 16) accs[w][lane] = acc;
        __syncthreads();
        if (tid < 16)
            g_ug2bits[a*16 + tid] = accs[0][tid] | accs[1][tid] | accs[2][tid] | accs[3][tid];
    } else {
        __shared__ int ired[4];
        int p = blockIdx.y - 1;
        int kcnt = (p == 0) ? N0 : (p == 1) ? N1 : N2;
        const float* sc = g_scores + p*NFULL;
        float s = sc[a];
        int r = 0;
        for (int b = tid; b < NFULL; b += 128){
            float sb = sc[b];
            r += (sb > s) || (sb == s && b < a);
        }
        for (int off = 16; off; off >>= 1) r += __shfl_xor_sync(0xffffffffu, r, off);
        if (lane == 0) ired[w] = r;
        __syncthreads();
        if (tid == 0){
            int rt = ired[0] + ired[1] + ired[2] + ired[3];
            if (rt < kcnt) g_idx[p*NFULL + rt] = a;
        }
    }
}

// ---------------- launch 2: prep = gather + gsub + layer0 A/B + inits ----------------
__global__ void k_prep(const float* __restrict__ feat, const float* __restrict__ coor,
                       const float* __restrict__ We1, const float* __restrict__ be1){
    __shared__ float h[DIMF];
    int p, i, n; pool_of(blockIdx.x, p, i, n);
    const int* idx = g_idx + p*NFULL;
    int a = idx[i];
    int tid = threadIdx.x, lane = tid & 31;
    float s = g_scores[p*NFULL + a];
    if (tid < DIMF){
        float v = feat[a*DIMF + tid] * s;
        h[tid] = v;
        g_hc[p*NMAX*DIMF + i*DIMF + tid] = v;
    } else if (tid < DIMF + 3){
        int c = tid - DIMF;
        float cv = coor[a*3 + c];
        g_cA[p*NMAX*3 + i*3 + c] = cv;
        g_cB[p*NMAX*3 + i*3 + c] = cv;
    } else if (tid < DIMF + 3 + MD){
        g_mi[p*NMAX*MD + i*MD + (tid - DIMF - 3)] = 0.0f;
    } else if (tid >= 128){
        int w = (tid >> 5) - 4;  // 0..3, full warps
        for (int q = 0; q < 4; q++){
            int wd = w*4 + q, j = wd*32 + lane;
            bool bit = false;
            if (j < n){
                int gj = idx[j];
                bit = (g_ug2bits[a*16 + (gj>>5)] >> (gj&31)) & 1u;
            }
            unsigned m = __ballot_sync(0xffffffffu, bit);
            if (lane == 0) g_gsub[p*NMAX*16 + i*16 + wd] = m;
        }
    }
    __syncthreads();
    float* Ar = g_Arow + p*NMAX*H1 + i*H1;
    float* Br = g_Brow + p*NMAX*H1 + i*H1;
    for (int k = tid; k < H1; k += 256){
        float av = be1[k], bv = 0.0f;
        #pragma unroll
        for (int d = 0; d < DIMF; d++){
            av = fmaf(h[d], We1[d*H1 + k], av);
            bv = fmaf(h[d], We1[(DIMF + d)*H1 + k], bv);
        }
        Ar[k] = av;
        Br[k] = bv;
    }
}

// ---------------- launch 3: the heavy edge kernel (all 3 pools, 12 warps x 2 rows) ----------------
__global__ void __launch_bounds__(ETHR, 2) k_edge(int flag,
    const float* __restrict__ We1L, const float* __restrict__ We2L,
    const float* __restrict__ be2L, const float* __restrict__ Wc1L,
    const float* __restrict__ bc1L, const float* __restrict__ Wc2L,
    const float* __restrict__ bc2L)
{
    extern __shared__ float sm[];
    float* ws   = sm;               // 260*20: We2 k-rows, t-linear (17 used + 3 zero)
    float* Bs   = ws + 5200;        // 260*33: B tile, k-major, conflict-free
    float* As2  = Bs + 8580;        // 260*24: A tile, k-major, 24 rows
    float* wded = As2 + 6240;       // 260*4: (wd,wd,we,we) -> one LDS.128
    float* wc1d = wded + 1040;      // 17*136: Wc1 duplicated pairs
    float* bc1d = wc1d + 2312;      // 136 (duplicated)
    float* wc2d = bc1d + 136;       // 136 (duplicated)
    float* be2p = wc2d + 136;       // 20 (t-linear, 17 used + 3 zero)
    float* cj   = be2p + 20;        // 96
    float* bc2s = cj + 96;          // 4  -> 23764 floats = 95056 B

    // pool decode
    int bid = blockIdx.x, p, lb, gx, nspl, n, nch;
    if (bid < 140){ p = 0; lb = bid;       gx = 20; nspl = 7; n = N0; nch = 15; }
    else if (bid < 230){ p = 1; lb = bid - 140; gx = 15; nspl = 6; n = N1; nch = 12; }
    else { p = 2; lb = bid - 230; gx = 13; nspl = 5; n = N2; nch = 10; }
    int bx = lb % gx, by = lb / gx;

    const float* Arow = g_Arow + p*NMAX*H1;
    const float* Brow = g_Brow + p*NMAX*H1;
    const uint32_t* gsub = g_gsub + p*NMAX*16;
    float* mi = g_mi + p*NMAX*MD;
    const float* ccur = (flag ? g_cB : g_cA) + p*NMAX*3;
    float*       cnext = (flag ? g_cA : g_cB) + p*NMAX*3;

    int tid = threadIdx.x, lane = tid & 31, wi = tid >> 5;
    const ull HALF2 = dup2(0.5f);

    // ---- stage weights ----
    for (int t = tid; t < 5200; t += ETHR){
        int k = t / 20, c = t - 20*k;
        ws[t] = (c < MD) ? We2L[k*MD + c] : 0.0f;
    }
    for (int t = tid; t < H1; t += ETHR){
        float wd = We1L[128*H1 + t], we = We1L[129*H1 + t];
        wded[4*t+0] = wd; wded[4*t+1] = wd; wded[4*t+2] = we; wded[4*t+3] = we;
    }
    for (int e = tid; e < MD*CHID; e += ETHR){
        int t = e / CHID, h = e - t*CHID;
        float v = Wc1L[e];
        wc1d[t*136 + 2*h] = v; wc1d[t*136 + 2*h + 1] = v;
    }
    if (tid < CHID){
        float v1 = bc1L[tid]; bc1d[2*tid] = v1; bc1d[2*tid+1] = v1;
        float v2 = Wc2L[tid]; wc2d[2*tid] = v2; wc2d[2*tid+1] = v2;
    }
    if (tid < 20) be2p[tid] = (tid < MD) ? be2L[tid] : 0.0f;
    if (tid == 0) bc2s[0] = bc2L[0];

    // ---- stage A tile (24 rows) ----
    int i0 = bx * RPB;
    for (int e = tid; e < RPB*H1; e += ETHR){
        int r = e / H1, k = e - r*H1;
        int ii = i0 + r;
        As2[k*RPB + r] = (ii < n) ? Arow[ii*H1 + k] : 0.0f;
    }
    __syncthreads();
    const float bc2v = bc2s[0];

    int ia = i0 + 2*wi, ib = ia + 1;
    bool iv0 = (ia < n), iv1 = (ib < n);
    float c0x=0,c0y=0,c0z=0,c1x=0,c1y=0,c1z=0;
    if (iv0){ c0x=ccur[ia*3];  c0y=ccur[ia*3+1];  c0z=ccur[ia*3+2]; }
    if (iv1){ c1x=ccur[ib*3];  c1y=ccur[ib*3+1];  c1z=ccur[ib*3+2]; }

    const ull* bc1u = (const ull*)bc1d;
    const ull* wc2u = (const ull*)wc2d;

    for (int ch = by; ch < nch; ch += nspl){
        int j0 = ch << 5;
        __syncthreads();
        for (int e = tid; e < 32*H1; e += ETHR){
            int jj = e / H1, k = e - jj*H1;
            int j = j0 + jj;
            Bs[k*33 + jj] = (j < n) ? Brow[j*H1 + k] : 0.0f;
        }
        for (int t = tid; t < 96; t += ETHR){
            int c = t / 32, jj = t - c*32;
            int j = j0 + jj;
            cj[t] = (j < n) ? ccur[j*3 + c] : 0.0f;
        }
        __syncthreads();
        if (!iv0) continue;   // staging/syncs above run unconditionally

        int j = j0 + lane;
        bool jv = (j < n);
        float jx = cj[lane], jy = cj[32+lane], jz = cj[64+lane];
        float r0x=c0x-jx, r0y=c0y-jy, r0z=c0z-jz;
        float r1x=c1x-jx, r1y=c1y-jy, r1z=c1z-jz;
        ull dd01 = pk2(r0x*r0x+r0y*r0y+r0z*r0z, r1x*r1x+r1y*r1y+r1z*r1z);
        uint32_t gb0 = iv0 ? gsub[ia*16 + ch] : 0u;
        uint32_t gb1 = iv1 ? gsub[ib*16 + ch] : 0u;
        ull ge01 = pk2(((gb0>>lane)&1u)?1.0f:0.0f, ((gb1>>lane)&1u)?1.0f:0.0f);

        // t-packed accumulators: m_a (row ia), m_b (row ib), 9 pairs each
        ull m_a[9], m_b[9];
        const ull* be2u = (const ull*)be2p;
        #pragma unroll
        for (int tp = 0; tp < 9; tp++){ m_a[tp] = be2u[tp]; m_b[tp] = m_a[tp]; }

        #pragma unroll 4
        for (int k = 0; k < H1; k++){
            ull ap = *(const ull*)(As2 + k*RPB + 2*wi);          // (A_ia, A_ib)
            ulonglong2 ww = *(const ulonglong2*)(wded + (k<<2)); // ((wd,wd),(we,we))
            ull bsvd = dup2(Bs[k*33 + lane]);
            ull pre = add2(ap, bsvd);
            pre = fma2(dd01, ww.x, pre);
            pre = fma2(ge01, ww.y, pre);
            ull s01 = silu2t(pre, HALF2);
            float s0, s1; unpk(s01, s0, s1);
            ull s0d = dup2(s0), s1d = dup2(s1);
            const ulonglong2* q2 = (const ulonglong2*)(ws + k*20);
            #pragma unroll
            for (int pp = 0; pp < 4; pp++){
                ulonglong2 qq = q2[pp];
                m_a[2*pp]   = fma2(s0d, qq.x, m_a[2*pp]);
                m_a[2*pp+1] = fma2(s0d, qq.y, m_a[2*pp+1]);
                m_b[2*pp]   = fma2(s1d, qq.x, m_b[2*pp]);
                m_b[2*pp+1] = fma2(s1d, qq.y, m_b[2*pp+1]);
            }
            {
                ull q8 = *(const ull*)(ws + k*20 + 16);
                m_a[8] = fma2(s0d, q8, m_a[8]);
                m_b[8] = fma2(s1d, q8, m_b[8]);
            }
        }

        // unpack t-pairs -> exact silu -> repack as row-pairs me01[t] = (me_ia, me_ib)
        ull me01[MD];
        #pragma unroll
        for (int tp = 0; tp < 9; tp++){
            float a0, a1, b0, b1;
            unpk(m_a[tp], a0, a1); unpk(m_b[tp], b0, b1);
            me01[2*tp] = silu2x(pk2(a0, b0));
            if (2*tp + 1 < MD) me01[2*tp+1] = silu2x(pk2(a1, b1));
        }

        // coor MLP, row-pair packed, 2 hidden units per iter
        ull cw01 = dup2(bc2v);
        #pragma unroll 2
        for (int h2 = 0; h2 < CHID/2; h2++){
            ull a0 = bc1u[2*h2], a1 = bc1u[2*h2+1];
            #pragma unroll
            for (int t = 0; t < MD; t++){
                ulonglong2 wwp = ((const ulonglong2*)(wc1d + t*136))[h2];
                a0 = fma2(me01[t], wwp.x, a0);
                a1 = fma2(me01[t], wwp.y, a1);
            }
            a0 = silu2x(a0); a1 = silu2x(a1);
            cw01 = fma2(a0, wc2u[2*h2],   cw01);
            cw01 = fma2(a1, wc2u[2*h2+1], cw01);
        }

        float mask = jv ? 1.0f : 0.0f;
        ull mask2 = dup2(mask);

        // m_i reduction (row-pair packed)
        #pragma unroll
        for (int t = 0; t < MD; t++){
            ull v = mul2(me01[t], mask2);
            v = add2(v, shflx2(v, 16)); v = add2(v, shflx2(v, 8));
            v = add2(v, shflx2(v, 4));  v = add2(v, shflx2(v, 2));
            v = add2(v, shflx2(v, 1));
            if (lane == 0){
                float va, vb; unpk(v, va, vb);
                atomicAdd(&mi[ia*MD + t], va);
                if (iv1) atomicAdd(&mi[ib*MD + t], vb);
            }
        }

        // coor update reduction (row-pair packed)
        ull vx = mul2(mul2(cw01, pk2(r0x, r1x)), mask2);
        ull vy = mul2(mul2(cw01, pk2(r0y, r1y)), mask2);
        ull vz = mul2(mul2(cw01, pk2(r0z, r1z)), mask2);
        #pragma unroll
        for (int off = 16; off; off >>= 1){
            vx = add2(vx, shflx2(vx, off));
            vy = add2(vy, shflx2(vy, off));
            vz = add2(vz, shflx2(vz, off));
        }
        if (lane == 0){
            float xa,xb,ya,yb,za,zb;
            unpk(vx,xa,xb); unpk(vy,ya,yb); unpk(vz,za,zb);
            atomicAdd(&cnext[ia*3+0], xa); atomicAdd(&cnext[ia*3+1], ya); atomicAdd(&cnext[ia*3+2], za);
            if (iv1){ atomicAdd(&cnext[ib*3+0], xb); atomicAdd(&cnext[ib*3+1], yb); atomicAdd(&cnext[ib*3+2], zb); }
        }
    }
}

// ---------------- node MLP + next-layer A/B (all 3 pools) ----------------
__global__ void k_nodeAB(const float* __restrict__ Wn1L, const float* __restrict__ bn1L,
                         const float* __restrict__ Wn2L, const float* __restrict__ bn2L,
                         const float* __restrict__ We1N, const float* __restrict__ be1N,
                         int do_ab, int flag_next){
    __shared__ float in[81];
    __shared__ float z[128];
    __shared__ float hnew[DIMF];
    int p, i, n; pool_of(blockIdx.x, p, i, n);
    (void)n;
    int tid = threadIdx.x;
    float* hc = g_hc + p*NMAX*DIMF + i*DIMF;
    float* miP = g_mi + p*NMAX*MD + i*MD;
    if (tid < DIMF) in[tid] = hc[tid];
    else if (tid < 81) in[tid] = miP[tid - DIMF];
    __syncthreads();
    if (tid < 128){
        float acc = bn1L[tid];
        #pragma unroll 1
        for (int k = 0; k < 81; k++) acc = fmaf(in[k], Wn1L[k*128 + tid], acc);
        z[tid] = siluf(acc);
    }
    __syncthreads();
    if (tid < DIMF){
        float a2 = bn2L[tid];
        #pragma unroll 1
        for (int k = 0; k < 128; k++) a2 = fmaf(z[k], Wn2L[k*DIMF + tid], a2);
        float v = fmaxf(2.0f*in[tid] + a2, 0.0f);
        hnew[tid] = v;
        hc[tid] = v;
    }
    if (!do_ab) return;
    if (tid >= DIMF && tid < DIMF + MD) miP[tid - DIMF] = 0.0f;
    else if (tid >= DIMF + MD && tid < DIMF + MD + 3){
        int c = tid - DIMF - MD;
        float* cn = (flag_next ? g_cA : g_cB) + p*NMAX*3;
        const float* cc = (flag_next ? g_cB : g_cA) + p*NMAX*3;
        cn[i*3 + c] = cc[i*3 + c];
    }
    __syncthreads();
    float* Ar = g_Arow + p*NMAX*H1 + i*H1;
    float* Br = g_Brow + p*NMAX*H1 + i*H1;
    for (int k = tid; k < H1; k += 256){
        float a = be1N[k], b = 0.0f;
        #pragma unroll
        for (int d = 0; d < DIMF; d++){
            a = fmaf(hnew[d], We1N[d*H1 + k], a);
            b = fmaf(hnew[d], We1N[(DIMF + d)*H1 + k], b);
        }
        Ar[k] = a;
        Br[k] = b;
    }
}

// ---------------- final scatter with max-merge (values >= 0, out pre-zeroed) ----------------
__global__ void k_scatter(float* out){
    int p, i, n; pool_of(blockIdx.x, p, i, n);
    (void)n;
    int t = threadIdx.x;
    int a = g_idx[p*NFULL + i];
    float v = g_hc[p*NMAX*DIMF + i*DIMF + t];
    atomicMax((int*)&out[a*DIMF + t], __float_as_int(v));
}

// ---------------- host ----------------
extern "C" void kernel_launch(void* const* d_in, const int* in_sizes, int n_in,
                              void* d_out, int out_size){
    const float* feat = (const float*)d_in[0];
    const float* coor = (const float*)d_in[1];
    const float* edge = (const float*)d_in[2];
    const float* We1  = (const float*)d_in[3];
    const float* be1  = (const float*)d_in[4];
    const float* We2  = (const float*)d_in[5];
    const float* be2  = (const float*)d_in[6];
    const float* Wc1  = (const float*)d_in[7];
    const float* bc1  = (const float*)d_in[8];
    const float* Wc2  = (const float*)d_in[9];
    const float* bc2  = (const float*)d_in[10];
    const float* Wn1  = (const float*)d_in[11];
    const float* bn1  = (const float*)d_in[12];
    const float* Wn2  = (const float*)d_in[13];
    const float* bn2  = (const float*)d_in[14];
    const float* wp   = (const float*)d_in[15];
    const float* bp   = (const float*)d_in[16];
    float* out = (float*)d_out;

    const int EDGE_SMEM = 23764 * 4;   // 95056 B
    cudaFuncSetAttribute(k_edge, cudaFuncAttributeMaxDynamicSharedMemorySize, EDGE_SMEM);

    k_ugbits_scores<<<512, 512>>>(edge, feat, wp, bp);  // 0
    k_ug2rank<<<dim3(NFULL, 4), 128>>>();               // 1 (ug2 + rank fused)
    k_prep<<<NTOT, 256>>>(feat, coor, We1, be1);        // 2
    k_edge<<<EGRID, ETHR, EDGE_SMEM>>>(0,               // 3  <- ncu capture slot
        We1, We2, be2, Wc1, bc1, Wc2, bc2);
    k_zero_out<<<128, 256>>>(out);                      // 4
    k_nodeAB<<<NTOT, 256>>>(                            // 5
        Wn1, bn1, Wn2, bn2, We1 + 130*H1, be1 + H1, 1, 1);
    for (int l = 1; l < 3; l++){
        k_edge<<<EGRID, ETHR, EDGE_SMEM>>>(l & 1,       // 6, 8
            We1 + l*130*H1, We2 + l*H1*MD, be2 + l*MD,
            Wc1 + l*MD*CHID, bc1 + l*CHID, Wc2 + l*CHID, bc2 + l);
        int ln = (l < 2) ? (l + 1) : 2;
        k_nodeAB<<<NTOT, 256>>>(                        // 7, 9
            Wn1 + l*81*128, bn1 + l*128, Wn2 + l*128*DIMF, bn2 + l*DIMF,
            We1 + ln*130*H1, be1 + ln*H1,
            (l < 2) ? 1 : 0, (l + 1) & 1);
    }
    k_scatter<<<NTOT, 64>>>(out);                       // 10
}